// round 4
// baseline (speedup 1.0000x reference)
#include <cuda_runtime.h>
#include <cuda_bf16.h>
#include <cstdint>

// Problem dims
#define SEQ 512
#define BATCH 16
#define EMB 512
#define SB 8192           // SEQ*BATCH rows
#define DFF 2048
#define DSS 128
#define SDEPTH 48
#define SWIDTH 128
#define NHEADS 8
#define HDIM 64

// ---------------- scratch (device globals; no allocation) ----------------
__device__ float g_h1 [SB * EMB];
__device__ float g_qkv[SB * 3 * EMB];
__device__ float g_att[SB * EMB];
__device__ float g_x  [SB * EMB];
__device__ float g_lg [SB * DSS];
__device__ float g_si [SB * SWIDTH];
__device__ float g_ctl[SB * 3];
__device__ float g_h2 [SB * EMB];
__device__ float g_f1 [SB * DFF];

#define NB_SYNC(id, cnt)   asm volatile("bar.sync %0, %1;"   :: "r"(id), "r"(cnt) : "memory")
#define NB_ARRIVE(id, cnt) asm volatile("bar.arrive %0, %1;" :: "r"(id), "r"(cnt) : "memory")

// ---------------- helpers ----------------
__device__ __forceinline__ float nonsat_f(float x) {
    // Newton for y^3/3 + y = x ; reference's step() IS the Newton update.
    float y = x;
#pragma unroll
    for (int i = 0; i < 20; i++) {
        float y2 = y * y;
        y = __fdividef(0.6666666666666666f * y2 * y + x, y2 + 1.0f);
    }
    return y;
}

__device__ __forceinline__ uint32_t to_tf32(float x) {
    uint32_t r;
    asm("cvt.rna.tf32.f32 %0, %1;" : "=r"(r) : "f"(x));
    return r;
}

__device__ __forceinline__ void mma_tf32(float (&c)[4], const uint32_t (&a)[4], const uint32_t (&b)[2]) {
    asm volatile(
        "mma.sync.aligned.m16n8k8.row.col.f32.tf32.tf32.f32 "
        "{%0,%1,%2,%3},{%4,%5,%6,%7},{%8,%9},{%0,%1,%2,%3};"
        : "+f"(c[0]), "+f"(c[1]), "+f"(c[2]), "+f"(c[3])
        : "r"(a[0]), "r"(a[1]), "r"(a[2]), "r"(a[3]), "r"(b[0]), "r"(b[1]));
}

// ---------------- GEMM: C[M,N] = A[M,K] @ W[N,K]^T + epilogue ----------------
struct GemmArgs {
    const float* A0; const float* A1; const float* A2;
    const float* W0; const float* W1; const float* W2;
    const float* b0; const float* b1; const float* b2;
    const float* res;
    float* C;
    int M, N, K;
};

// MODE: 0=+bias  1=+bias,relu  2=+bias+res  3=hidden(3src,+3bias,nonsat)
//       4=logits(2src,nobias)  5=mix(res: 0.5*(res+acc))  6=+bias,nonsat
template<int MODE>
__device__ __forceinline__ float4 loadA(const GemmArgs& P, int grow, int gk) {
    if constexpr (MODE == 3) {
        if (gk < 512) {
            // grow = b*512+s (hidden order); x lives in (s,b) order
            int xr = ((grow & 511) << 4) + (grow >> 9);
            return *(const float4*)&P.A0[(size_t)xr * 512 + gk];
        } else if (gk < 1024) {
            return *(const float4*)&P.A1[(size_t)grow * 512 + (gk - 512)];
        } else {
            return *(const float4*)&P.A2[(size_t)grow * (SDEPTH * SWIDTH) + (gk - 1024)];
        }
    } else if constexpr (MODE == 4) {
        if (gk < 512) return *(const float4*)&P.A0[(size_t)grow * 512 + gk];
        // grow = s*16+b (x order); hidden lives in (b,s) order
        int hr = ((grow & 15) << 9) + (grow >> 4);
        return *(const float4*)&P.A1[(size_t)hr * 512 + (gk - 512)];
    } else {
        return *(const float4*)&P.A0[(size_t)grow * P.K + gk];
    }
}

template<int MODE>
__device__ __forceinline__ float4 loadW(const GemmArgs& P, int n, int gk) {
    if constexpr (MODE == 3) {
        if (gk < 512)       return *(const float4*)&P.W0[(size_t)n * 512 + gk];
        else if (gk < 1024) return *(const float4*)&P.W1[(size_t)n * 512 + (gk - 512)];
        else                return *(const float4*)&P.W2[(size_t)n * 128 + (gk - 1024)];
    } else {
        return *(const float4*)&P.W0[(size_t)n * P.K + gk];
    }
}

// Warp-specialized 128x128x16 pipeline.
// threads 0..255  : 8 consumer warps (2x4), each 64x32 via 4x4 m16n8k8 tf32 MMAs
// threads 256..383: 4 producer warps: LDG -> cvt.tf32 -> STS fragment-packed
// Named barriers: FULL_b (id 1+b), EMPTY_b (id 3+b), count = 384.
template<int MODE>
__global__ void __launch_bounds__(384) gemm_tc(GemmArgs P) {
    __shared__ uint32_t As[2][2048];
    __shared__ uint32_t Bs[2][2048];

    const int tid  = threadIdx.x;
    const int bn = blockIdx.x, bm = blockIdx.y;
    const int row0 = bm * 128, col0 = bn * 128;
    const int nst = P.K >> 4;

    if (tid >= 256) {
        // ---------------- producer ----------------
        const int pt = tid - 256;        // 0..127
        const int r0 = pt >> 2;          // 0..31
        const int c4 = pt & 3;
        const int ks_st  = c4 >> 1;
        const int khi_st = c4 & 1;

        float4 pa[4], pw[4];
        // prefetch stage 0
#pragma unroll
        for (int li = 0; li < 4; li++) {
            int r = r0 + li * 32;
            pa[li] = loadA<MODE>(P, row0 + r, c4 * 4);
            pw[li] = loadW<MODE>(P, col0 + r, c4 * 4);
        }
        for (int s = 0; s < nst; s++) {
            const int b = s & 1;
            if (s >= 2) NB_SYNC(3 + b, 384);      // wait consumers done with buffer b
#pragma unroll
            for (int li = 0; li < 4; li++) {
                int r = r0 + li * 32;
                int tm = r >> 4, gA = r & 7, hiA = (r >> 3) & 1;
                uint32_t* dA = &As[b][(tm * 2 + ks_st) * 128 + gA * 16 + hiA + 2 * khi_st];
                dA[0]  = to_tf32(pa[li].x);
                dA[4]  = to_tf32(pa[li].y);
                dA[8]  = to_tf32(pa[li].z);
                dA[12] = to_tf32(pa[li].w);
                int tn = r >> 3, gB = r & 7;
                uint32_t* dB = &Bs[b][(tn * 2 + ks_st) * 64 + gB * 8 + khi_st];
                dB[0] = to_tf32(pw[li].x);
                dB[2] = to_tf32(pw[li].y);
                dB[4] = to_tf32(pw[li].z);
                dB[6] = to_tf32(pw[li].w);
            }
            NB_ARRIVE(1 + b, 384);                // publish buffer b
            if (s + 1 < nst) {
                int kt = (s + 1) << 4;
#pragma unroll
                for (int li = 0; li < 4; li++) {
                    int r = r0 + li * 32;
                    pa[li] = loadA<MODE>(P, row0 + r, kt + c4 * 4);
                    pw[li] = loadW<MODE>(P, col0 + r, kt + c4 * 4);
                }
            }
        }
        return;
    }

    // ---------------- consumer ----------------
    const int lane = tid & 31;
    const int warp = tid >> 5;
    const int wm = warp >> 2;           // 0..1
    const int wn = warp & 3;            // 0..3

    float acc[4][4][4];
#pragma unroll
    for (int i = 0; i < 4; i++)
#pragma unroll
        for (int j = 0; j < 4; j++)
#pragma unroll
            for (int e = 0; e < 4; e++) acc[i][j][e] = 0.f;

    for (int s = 0; s < nst; s++) {
        const int b = s & 1;
        NB_SYNC(1 + b, 384);                      // wait buffer b full
#pragma unroll
        for (int ks = 0; ks < 2; ks++) {
            uint32_t af[4][4];
            uint32_t bf[4][2];
#pragma unroll
            for (int tmi = 0; tmi < 4; tmi++) {
                const uint4 v = *(const uint4*)&As[b][(((wm * 4 + tmi) * 2 + ks) * 32 + lane) * 4];
                af[tmi][0] = v.x; af[tmi][1] = v.y; af[tmi][2] = v.z; af[tmi][3] = v.w;
            }
#pragma unroll
            for (int tni = 0; tni < 4; tni++) {
                const uint2 v = *(const uint2*)&Bs[b][(((wn * 4 + tni) * 2 + ks) * 32 + lane) * 2];
                bf[tni][0] = v.x; bf[tni][1] = v.y;
            }
#pragma unroll
            for (int tmi = 0; tmi < 4; tmi++)
#pragma unroll
                for (int tni = 0; tni < 4; tni++)
                    mma_tf32(acc[tmi][tni], af[tmi], bf[tni]);
        }
        NB_ARRIVE(3 + b, 384);                    // release buffer b
    }

    // epilogue: C-fragment c0,c1 -> (row=g, col=q*2, q*2+1); c2,c3 -> row+8
    const int g = lane >> 2, q = lane & 3;
#pragma unroll
    for (int tmi = 0; tmi < 4; tmi++) {
        int rb = row0 + wm * 64 + tmi * 16;
#pragma unroll
        for (int h2 = 0; h2 < 2; h2++) {
            int gm = rb + g + h2 * 8;
#pragma unroll
            for (int tni = 0; tni < 4; tni++) {
                int gn = col0 + wn * 32 + tni * 8 + q * 2;
                float v0 = acc[tmi][tni][h2 * 2 + 0];
                float v1 = acc[tmi][tni][h2 * 2 + 1];
                if constexpr (MODE == 0) { v0 += P.b0[gn]; v1 += P.b0[gn + 1]; }
                else if constexpr (MODE == 1) {
                    v0 = fmaxf(v0 + P.b0[gn], 0.f);
                    v1 = fmaxf(v1 + P.b0[gn + 1], 0.f);
                } else if constexpr (MODE == 2) {
                    const float* rp = &P.res[(size_t)gm * P.N + gn];
                    v0 = v0 + P.b0[gn] + rp[0];
                    v1 = v1 + P.b0[gn + 1] + rp[1];
                } else if constexpr (MODE == 3) {
                    v0 = nonsat_f(v0 + P.b0[gn] + P.b1[gn] + P.b2[gn]);
                    v1 = nonsat_f(v1 + P.b0[gn + 1] + P.b1[gn + 1] + P.b2[gn + 1]);
                } else if constexpr (MODE == 4) {
                    /* raw */
                } else if constexpr (MODE == 5) {
                    const float* rp = &P.res[(size_t)gm * P.N + gn];
                    v0 = 0.5f * (rp[0] + v0);
                    v1 = 0.5f * (rp[1] + v1);
                } else if constexpr (MODE == 6) {
                    v0 = nonsat_f(v0 + P.b0[gn]);
                    v1 = nonsat_f(v1 + P.b0[gn + 1]);
                }
                *(float2*)&P.C[(size_t)gm * P.N + gn] = make_float2(v0, v1);
            }
        }
    }
}

// ---------------- LayerNorm (row of 512) ----------------
__global__ void __launch_bounds__(128) ln_kernel(const float* __restrict__ x,
                                                 const float* __restrict__ g,
                                                 const float* __restrict__ b,
                                                 float* __restrict__ out) {
    const int r = blockIdx.x, t = threadIdx.x;
    const float* row = x + (size_t)r * 512;
    float v0 = row[t], v1 = row[t + 128], v2 = row[t + 256], v3 = row[t + 384];
    __shared__ float sh[4];
    float s = v0 + v1 + v2 + v3;
#pragma unroll
    for (int o = 16; o; o >>= 1) s += __shfl_xor_sync(0xffffffffu, s, o);
    if ((t & 31) == 0) sh[t >> 5] = s;
    __syncthreads();
    float mean = (sh[0] + sh[1] + sh[2] + sh[3]) * (1.f / 512.f);
    __syncthreads();
    float d0 = v0 - mean, d1 = v1 - mean, d2 = v2 - mean, d3 = v3 - mean;
    float q = d0 * d0 + d1 * d1 + d2 * d2 + d3 * d3;
#pragma unroll
    for (int o = 16; o; o >>= 1) q += __shfl_xor_sync(0xffffffffu, q, o);
    if ((t & 31) == 0) sh[t >> 5] = q;
    __syncthreads();
    float var = (sh[0] + sh[1] + sh[2] + sh[3]) * (1.f / 512.f);
    float rstd = rsqrtf(var + 1e-5f);
    float* orow = out + (size_t)r * 512;
    orow[t]       = d0 * rstd * g[t]       + b[t];
    orow[t + 128] = d1 * rstd * g[t + 128] + b[t + 128];
    orow[t + 256] = d2 * rstd * g[t + 256] + b[t + 256];
    orow[t + 384] = d3 * rstd * g[t + 384] + b[t + 384];
}

// ---------------- Flash attention (64x64 tiles, causal) ----------------
__global__ void __launch_bounds__(256) attn_kernel(const float* __restrict__ qkv,
                                                   const unsigned char* __restrict__ kmask,
                                                   float* __restrict__ out) {
    extern __shared__ float sm[];
    float* Qt   = sm;                // [64 d][68] transposed, pre-scaled
    float* Kt   = Qt + 64 * 68;      // [64 d][68]
    float* Pt   = Kt + 64 * 68;      // scores/probs transposed [c][68 -> r]
    float* Vs   = Pt + 64 * 68;      // [c][68 -> d]
    float* mrow = Vs + 64 * 68;      // 64
    float* lrow = mrow + 64;         // 64
    float* rsc  = lrow + 64;         // 64
    float* kmf  = rsc + 64;          // 64

    const int tid = threadIdx.x;
    const int qt = blockIdx.x;       // 0..7
    const int bh = blockIdx.y;       // 0..127
    const int b = bh >> 3, h = bh & 7;
    const int ty = tid >> 4, tx = tid & 15;

#pragma unroll
    for (int li = 0; li < 4; li++) {
        int idx = tid + li * 256;
        int r = idx >> 4, d4 = idx & 15;
        float4 q = *(const float4*)&qkv[(size_t)((qt * 64 + r) * 16 + b) * 1536 + h * 64 + d4 * 4];
        Qt[(d4 * 4 + 0) * 68 + r] = q.x * 0.125f;
        Qt[(d4 * 4 + 1) * 68 + r] = q.y * 0.125f;
        Qt[(d4 * 4 + 2) * 68 + r] = q.z * 0.125f;
        Qt[(d4 * 4 + 3) * 68 + r] = q.w * 0.125f;
    }
    if (tid < 64) { mrow[tid] = -1e30f; lrow[tid] = 0.f; }
    float Oa[4][4];
#pragma unroll
    for (int i = 0; i < 4; i++)
#pragma unroll
        for (int j = 0; j < 4; j++) Oa[i][j] = 0.f;
    __syncthreads();

    for (int kt = 0; kt <= qt; kt++) {
#pragma unroll
        for (int li = 0; li < 4; li++) {
            int idx = tid + li * 256;
            int c = idx >> 4, d4 = idx & 15;
            size_t base = (size_t)((kt * 64 + c) * 16 + b) * 1536 + h * 64;
            float4 kv = *(const float4*)&qkv[base + 512 + d4 * 4];
            Kt[(d4 * 4 + 0) * 68 + c] = kv.x;
            Kt[(d4 * 4 + 1) * 68 + c] = kv.y;
            Kt[(d4 * 4 + 2) * 68 + c] = kv.z;
            Kt[(d4 * 4 + 3) * 68 + c] = kv.w;
            float4 vv = *(const float4*)&qkv[base + 1024 + d4 * 4];
            *(float4*)&Vs[c * 68 + d4 * 4] = vv;
        }
        if (tid < 64) kmf[tid] = kmask[b * 512 + kt * 64 + tid] ? -1e30f : 0.f;
        __syncthreads();

        float sc[4][4];
#pragma unroll
        for (int i = 0; i < 4; i++)
#pragma unroll
            for (int j = 0; j < 4; j++) sc[i][j] = 0.f;
#pragma unroll
        for (int d = 0; d < 64; d++) {
            float4 qa = *(const float4*)&Qt[d * 68 + ty * 4];
            float4 ka = *(const float4*)&Kt[d * 68 + tx * 4];
            float qr[4] = {qa.x, qa.y, qa.z, qa.w};
            float kr[4] = {ka.x, ka.y, ka.z, ka.w};
#pragma unroll
            for (int i = 0; i < 4; i++)
#pragma unroll
                for (int j = 0; j < 4; j++) sc[i][j] += qr[i] * kr[j];
        }
        const bool diag = (kt == qt);
#pragma unroll
        for (int j = 0; j < 4; j++) {
            int c = tx * 4 + j;
            float add = kmf[c];
            float vv[4];
#pragma unroll
            for (int i = 0; i < 4; i++) {
                int r = ty * 4 + i;
                float val = sc[i][j] + add;
                if (diag && c > r) val = -1e30f;
                vv[i] = val;
            }
            *(float4*)&Pt[c * 68 + ty * 4] = make_float4(vv[0], vv[1], vv[2], vv[3]);
        }
        __syncthreads();

        {
            int r = tid >> 2, q4 = tid & 3;
            float mx = -1e30f;
#pragma unroll
            for (int cc = 0; cc < 16; cc++) mx = fmaxf(mx, Pt[(q4 * 16 + cc) * 68 + r]);
            mx = fmaxf(mx, __shfl_xor_sync(0xffffffffu, mx, 1));
            mx = fmaxf(mx, __shfl_xor_sync(0xffffffffu, mx, 2));
            float mold = mrow[r];
            float mnew = fmaxf(mold, mx);
            float sum = 0.f;
#pragma unroll
            for (int cc = 0; cc < 16; cc++) {
                int c = q4 * 16 + cc;
                float p = __expf(Pt[c * 68 + r] - mnew);
                Pt[c * 68 + r] = p;
                sum += p;
            }
            sum += __shfl_xor_sync(0xffffffffu, sum, 1);
            sum += __shfl_xor_sync(0xffffffffu, sum, 2);
            if (q4 == 0) {
                float scale = __expf(mold - mnew);
                mrow[r] = mnew;
                lrow[r] = lrow[r] * scale + sum;
                rsc[r] = scale;
            }
        }
        __syncthreads();

#pragma unroll
        for (int i = 0; i < 4; i++) {
            float s0 = rsc[ty * 4 + i];
#pragma unroll
            for (int j = 0; j < 4; j++) Oa[i][j] *= s0;
        }
#pragma unroll
        for (int c = 0; c < 64; c++) {
            float4 pa = *(const float4*)&Pt[c * 68 + ty * 4];
            float4 va = *(const float4*)&Vs[c * 68 + tx * 4];
            float pr[4] = {pa.x, pa.y, pa.z, pa.w};
            float vr[4] = {va.x, va.y, va.z, va.w};
#pragma unroll
            for (int i = 0; i < 4; i++)
#pragma unroll
                for (int j = 0; j < 4; j++) Oa[i][j] += pr[i] * vr[j];
        }
        __syncthreads();
    }

#pragma unroll
    for (int i = 0; i < 4; i++) {
        int r = ty * 4 + i;
        float inv = __fdividef(1.f, lrow[r]);
        float4 o = make_float4(Oa[i][0] * inv, Oa[i][1] * inv, Oa[i][2] * inv, Oa[i][3] * inv);
        *(float4*)&out[(size_t)((qt * 64 + r) * 16 + b) * 512 + h * 64 + tx * 4] = o;
    }
}

// ---------------- softmax over 128 (mixture logits) ----------------
__global__ void __launch_bounds__(128) softmax128_kernel(float* __restrict__ lg) {
    const int r = blockIdx.x, t = threadIdx.x;
    float v = lg[(size_t)r * 128 + t];
    __shared__ float sh[4];
    float m = v;
#pragma unroll
    for (int o = 16; o; o >>= 1) m = fmaxf(m, __shfl_xor_sync(0xffffffffu, m, o));
    if ((t & 31) == 0) sh[t >> 5] = m;
    __syncthreads();
    m = fmaxf(fmaxf(sh[0], sh[1]), fmaxf(sh[2], sh[3]));
    float e = __expf(v - m);
    __syncthreads();
    float s = e;
#pragma unroll
    for (int o = 16; o; o >>= 1) s += __shfl_xor_sync(0xffffffffu, s, o);
    if ((t & 31) == 0) sh[t >> 5] = s;
    __syncthreads();
    s = sh[0] + sh[1] + sh[2] + sh[3];
    lg[(size_t)r * 128 + t] = e * __fdividef(1.f, s);
}

// ---------------- stack controls: softmax(hidden @ A_w^T + A_b) ----------------
__global__ void __launch_bounds__(128) controls_kernel(const float* __restrict__ hidden,
                                                       const float* __restrict__ Aw,
                                                       const float* __restrict__ Ab,
                                                       float* __restrict__ ctl) {
    const int r = blockIdx.x, t = threadIdx.x;
    const float* row = hidden + (size_t)r * 512;
    float s0 = 0.f, s1 = 0.f, s2 = 0.f;
#pragma unroll
    for (int i = 0; i < 4; i++) {
        int c = t + i * 128;
        float hv = row[c];
        s0 += hv * Aw[c];
        s1 += hv * Aw[512 + c];
        s2 += hv * Aw[1024 + c];
    }
    __shared__ float sh[3][4];
#pragma unroll
    for (int o = 16; o; o >>= 1) {
        s0 += __shfl_xor_sync(0xffffffffu, s0, o);
        s1 += __shfl_xor_sync(0xffffffffu, s1, o);
        s2 += __shfl_xor_sync(0xffffffffu, s2, o);
    }
    if ((t & 31) == 0) { sh[0][t >> 5] = s0; sh[1][t >> 5] = s1; sh[2][t >> 5] = s2; }
    __syncthreads();
    if (t == 0) {
        float c0 = sh[0][0] + sh[0][1] + sh[0][2] + sh[0][3] + Ab[0];
        float c1 = sh[1][0] + sh[1][1] + sh[1][2] + sh[1][3] + Ab[1];
        float c2 = sh[2][0] + sh[2][1] + sh[2][2] + sh[2][3] + Ab[2];
        float m = fmaxf(c0, fmaxf(c1, c2));
        float e0 = __expf(c0 - m), e1 = __expf(c1 - m), e2 = __expf(c2 - m);
        float inv = __fdividef(1.f, e0 + e1 + e2);
        ctl[r * 3 + 0] = e0 * inv;
        ctl[r * 3 + 1] = e1 * inv;
        ctl[r * 3 + 2] = e2 * inv;
    }
}

// ---------------- stack update ----------------
__global__ void __launch_bounds__(128) stack_kernel(const float* __restrict__ stack_prev,
                                                    const float* __restrict__ si,
                                                    const float* __restrict__ ctl,
                                                    float* __restrict__ out) {
    const int g = blockIdx.x;       // b*512+s
    const int w = threadIdx.x;      // 0..127
    const float* prev = stack_prev + (size_t)g * (SDEPTH * SWIDTH);
    float* o = out + (size_t)g * (SDEPTH * SWIDTH);
    const float cpush = ctl[g * 3 + 0];
    const float cpop  = ctl[g * 3 + 1];
    const float cnoop = ctl[g * 3 + 2];
    float pm1 = si[(size_t)g * 128 + w];   // push source at depth 0
    float p0 = prev[w];
#pragma unroll 4
    for (int d = 0; d < SDEPTH; d++) {
        float p1 = (d < SDEPTH - 1) ? prev[(d + 1) * SWIDTH + w] : 0.f;
        o[d * SWIDTH + w] = cnoop * p0 + cpush * pm1 + cpop * p1;
        pm1 = p0;
        p0 = p1;
    }
}

// ---------------- host ----------------
template<int MODE>
static void launch_gemm(const GemmArgs& P) {
    dim3 grid(P.N / 128, P.M / 128);
    gemm_tc<MODE><<<grid, 384>>>(P);
}

extern "C" void kernel_launch(void* const* d_in, const int* in_sizes, int n_in,
                              void* d_out, int out_size) {
    const float* x_in        = (const float*)d_in[0];
    const float* hidden_prev = (const float*)d_in[1];
    const float* stack_prev  = (const float*)d_in[2];
    const unsigned char* k_mask = (const unsigned char*)d_in[3];
    const float* in_proj_w  = (const float*)d_in[4];
    const float* in_proj_b  = (const float*)d_in[5];
    const float* out_proj_w = (const float*)d_in[6];
    const float* out_proj_b = (const float*)d_in[7];
    const float* ln1_g = (const float*)d_in[8];
    const float* ln1_b = (const float*)d_in[9];
    const float* ln2_g = (const float*)d_in[10];
    const float* ln2_b = (const float*)d_in[11];
    const float* ff_w1 = (const float*)d_in[12];
    const float* ff_b1 = (const float*)d_in[13];
    const float* ff_w2 = (const float*)d_in[14];
    const float* ff_b2 = (const float*)d_in[15];
    const float* W_w = (const float*)d_in[16];
    const float* W_b = (const float*)d_in[17];
    const float* R_w = (const float*)d_in[18];
    const float* R_b = (const float*)d_in[19];
    const float* P_w = (const float*)d_in[20];
    const float* P_b = (const float*)d_in[21];
    const float* V_w = (const float*)d_in[22];
    const float* U_w = (const float*)d_in[23];
    const float* A_w = (const float*)d_in[24];
    const float* A_b = (const float*)d_in[25];
    const float* D_w = (const float*)d_in[26];
    const float* D_b = (const float*)d_in[27];

    float *h1, *qkvb, *attb, *xb, *lg, *si, *ctl, *h2, *f1;
    cudaGetSymbolAddress((void**)&h1,  g_h1);
    cudaGetSymbolAddress((void**)&qkvb, g_qkv);
    cudaGetSymbolAddress((void**)&attb, g_att);
    cudaGetSymbolAddress((void**)&xb,  g_x);
    cudaGetSymbolAddress((void**)&lg,  g_lg);
    cudaGetSymbolAddress((void**)&si,  g_si);
    cudaGetSymbolAddress((void**)&ctl, g_ctl);
    cudaGetSymbolAddress((void**)&h2,  g_h2);
    cudaGetSymbolAddress((void**)&f1,  g_f1);

    float* out_x      = (float*)d_out;
    float* out_hidden = out_x + (size_t)SB * EMB;
    float* out_stack  = out_hidden + (size_t)SB * EMB;

    const int ATTN_SMEM = (4 * 64 * 68 + 4 * 64) * (int)sizeof(float);
    cudaFuncSetAttribute(attn_kernel, cudaFuncAttributeMaxDynamicSharedMemorySize, ATTN_SMEM);

    // 1. LN1
    ln_kernel<<<SB, 128>>>(x_in, ln1_g, ln1_b, h1);

    // 2. QKV projection
    {
        GemmArgs P{};
        P.A0 = h1; P.W0 = in_proj_w; P.b0 = in_proj_b; P.C = qkvb;
        P.M = SB; P.N = 3 * EMB; P.K = EMB;
        launch_gemm<0>(P);
    }

    // 3. Attention (causal flash)
    attn_kernel<<<dim3(SEQ / 64, BATCH * NHEADS), 256, ATTN_SMEM>>>(qkvb, k_mask, attb);

    // 4. Output projection + residual -> x
    {
        GemmArgs P{};
        P.A0 = attb; P.W0 = out_proj_w; P.b0 = out_proj_b; P.res = x_in; P.C = xb;
        P.M = SB; P.N = EMB; P.K = EMB;
        launch_gemm<2>(P);
    }

    // 5. hidden = nonsat(xb@W^T + hprev@R^T + stack_top@P^T + biases)
    {
        GemmArgs P{};
        P.A0 = xb; P.A1 = hidden_prev; P.A2 = stack_prev;
        P.W0 = W_w; P.W1 = R_w; P.W2 = P_w;
        P.b0 = W_b; P.b1 = R_b; P.b2 = P_b;
        P.C = out_hidden;
        P.M = SB; P.N = EMB; P.K = 1152;
        launch_gemm<3>(P);
    }

    // 6. logits = [x | hidden^T] @ V_w^T
    {
        GemmArgs P{};
        P.A0 = xb; P.A1 = out_hidden; P.W0 = V_w; P.C = lg;
        P.M = SB; P.N = DSS; P.K = 1024;
        launch_gemm<4>(P);
    }

    // 7. softmax over 128
    softmax128_kernel<<<SB, 128>>>(lg);

    // 8. x = 0.5*(x + p @ U_w^T)
    {
        GemmArgs P{};
        P.A0 = lg; P.W0 = U_w; P.res = xb; P.C = xb;
        P.M = SB; P.N = EMB; P.K = DSS;
        launch_gemm<5>(P);
    }

    // 9. stack_inp = nonsat(hidden @ D_w^T + D_b)
    {
        GemmArgs P{};
        P.A0 = out_hidden; P.W0 = D_w; P.b0 = D_b; P.C = si;
        P.M = SB; P.N = SWIDTH; P.K = EMB;
        launch_gemm<6>(P);
    }

    // 10. controls
    controls_kernel<<<SB, 128>>>(out_hidden, A_w, A_b, ctl);

    // 11. stack update
    stack_kernel<<<SB, 128>>>(stack_prev, si, ctl, out_stack);

    // 12. LN2
    ln_kernel<<<SB, 128>>>(xb, ln2_g, ln2_b, h2);

    // 13. FF1 (relu)
    {
        GemmArgs P{};
        P.A0 = h2; P.W0 = ff_w1; P.b0 = ff_b1; P.C = f1;
        P.M = SB; P.N = DFF; P.K = EMB;
        launch_gemm<1>(P);
    }

    // 14. FF2 + residual -> out_x
    {
        GemmArgs P{};
        P.A0 = f1; P.W0 = ff_w2; P.b0 = ff_b2; P.res = xb; P.C = out_x;
        P.M = SB; P.N = EMB; P.K = DFF;
        launch_gemm<2>(P);
    }
}

// round 9
// speedup vs baseline: 1.3259x; 1.3259x over previous
#include <cuda_runtime.h>
#include <cuda_bf16.h>
#include <cstdint>

// Problem dims
#define SEQ 512
#define BATCH 16
#define EMB 512
#define SB 8192           // SEQ*BATCH rows
#define DFF 2048
#define DSS 128
#define SDEPTH 48
#define SWIDTH 128
#define NHEADS 8
#define HDIM 64

// ---------------- scratch (device globals; no allocation) ----------------
__device__ float g_h1 [SB * EMB];
__device__ float g_qkv[SB * 3 * EMB];
__device__ float g_att[SB * EMB];
__device__ float g_x  [SB * EMB];
__device__ float g_lg [SB * DSS];
__device__ float g_si [SB * SWIDTH];
__device__ float g_ctl[SB * 3];
__device__ float g_h2 [SB * EMB];
__device__ float g_f1 [SB * DFF];

// ---------------- helpers ----------------
__device__ __forceinline__ float nonsat_f(float x) {
    // Newton for y^3/3 + y = x ; reference's step() IS the Newton update.
    float y = x;
#pragma unroll
    for (int i = 0; i < 20; i++) {
        float y2 = y * y;
        y = __fdividef(0.6666666666666666f * y2 * y + x, y2 + 1.0f);
    }
    return y;
}

__device__ __forceinline__ uint32_t to_tf32(float x) {
    uint32_t r;
    asm("cvt.rna.tf32.f32 %0, %1;" : "=r"(r) : "f"(x));
    return r;
}

__device__ __forceinline__ void mma_tf32(float (&c)[4], const uint32_t (&a)[4], const uint32_t (&b)[2]) {
    asm volatile(
        "mma.sync.aligned.m16n8k8.row.col.f32.tf32.tf32.f32 "
        "{%0,%1,%2,%3},{%4,%5,%6,%7},{%8,%9},{%0,%1,%2,%3};"
        : "+f"(c[0]), "+f"(c[1]), "+f"(c[2]), "+f"(c[3])
        : "r"(a[0]), "r"(a[1]), "r"(a[2]), "r"(a[3]), "r"(b[0]), "r"(b[1]));
}

// ---------------- GEMM: C[M,N] = A[M,K] @ W[N,K]^T + epilogue ----------------
struct GemmArgs {
    const float* A0; const float* A1; const float* A2;
    const float* W0; const float* W1; const float* W2;
    const float* b0; const float* b1; const float* b2;
    const float* res;
    float* C;
    int M, N, K;
};

// MODE: 0=+bias  1=+bias,relu  2=+bias+res  3=hidden(3src,+3bias,nonsat)
//       4=logits(2src,nobias)  5=mix(res: 0.5*(res+acc))  6=+bias,nonsat
template<int MODE>
__device__ __forceinline__ float4 loadA(const GemmArgs& P, int grow, int gk) {
    if constexpr (MODE == 3) {
        if (gk < 512) {
            // grow = b*512+s (hidden order); x lives in (s,b) order
            int xr = ((grow & 511) << 4) + (grow >> 9);
            return *(const float4*)&P.A0[(size_t)xr * 512 + gk];
        } else if (gk < 1024) {
            return *(const float4*)&P.A1[(size_t)grow * 512 + (gk - 512)];
        } else {
            return *(const float4*)&P.A2[(size_t)grow * (SDEPTH * SWIDTH) + (gk - 1024)];
        }
    } else if constexpr (MODE == 4) {
        if (gk < 512) return *(const float4*)&P.A0[(size_t)grow * 512 + gk];
        // grow = s*16+b (x order); hidden lives in (b,s) order
        int hr = ((grow & 15) << 9) + (grow >> 4);
        return *(const float4*)&P.A1[(size_t)hr * 512 + (gk - 512)];
    } else {
        return *(const float4*)&P.A0[(size_t)grow * P.K + gk];
    }
}

template<int MODE>
__device__ __forceinline__ float4 loadW(const GemmArgs& P, int n, int gk) {
    if constexpr (MODE == 3) {
        if (gk < 512)       return *(const float4*)&P.W0[(size_t)n * 512 + gk];
        else if (gk < 1024) return *(const float4*)&P.W1[(size_t)n * 512 + (gk - 512)];
        else                return *(const float4*)&P.W2[(size_t)n * 128 + (gk - 1024)];
    } else {
        return *(const float4*)&P.W0[(size_t)n * P.K + gk];
    }
}

// 128x128x16 tile, 256 threads = 8 warps (2 x 4). Each warp: 64 rows x 32 cols
// via 4x4 grid of m16n8k8 tf32 MMAs.
// Smem layout: [row][16 k] with crosswise swizzle: float4-group g' = g ^ ((row>>1)&3).
//   Producer: 1 conflict-free STS.128 per float4.
//   Consumer: conflict-free LDS.32 fragment gathers.
template<int MODE>
__global__ void __launch_bounds__(256) gemm_tc(GemmArgs P) {
    __shared__ uint32_t As[2][2048];
    __shared__ uint32_t Bs[2][2048];

    const int tid  = threadIdx.x;
    const int lane = tid & 31;
    const int warp = tid >> 5;
    const int wm = warp >> 2;           // 0..1
    const int wn = warp & 3;            // 0..3
    const int bn = blockIdx.x, bm = blockIdx.y;
    const int row0 = bm * 128, col0 = bn * 128;

    // loader indexing
    const int r0 = tid >> 2;            // 0..63 (li adds 64)
    const int c4 = tid & 3;             // which float4 along k

    // consumer indexing
    const int g  = lane >> 2;           // 0..7
    const int kq = lane & 3;            // 0..3
    const int swz = (g >> 1) & 3;

    float acc[4][4][4];
#pragma unroll
    for (int i = 0; i < 4; i++)
#pragma unroll
        for (int j = 0; j < 4; j++)
#pragma unroll
            for (int e = 0; e < 4; e++) acc[i][j][e] = 0.f;

    const int nst = P.K >> 4;

    float4 pa[2], pw[2];

    // prologue: load + store stage 0
#pragma unroll
    for (int li = 0; li < 2; li++) {
        int r = r0 + li * 64;
        pa[li] = loadA<MODE>(P, row0 + r, c4 * 4);
        pw[li] = loadW<MODE>(P, col0 + r, c4 * 4);
    }
#pragma unroll
    for (int li = 0; li < 2; li++) {
        int r = r0 + li * 64;
        int off = r * 16 + ((c4 ^ ((r >> 1) & 3)) << 2);
        *(uint4*)&As[0][off] = make_uint4(to_tf32(pa[li].x), to_tf32(pa[li].y),
                                          to_tf32(pa[li].z), to_tf32(pa[li].w));
        *(uint4*)&Bs[0][off] = make_uint4(to_tf32(pw[li].x), to_tf32(pw[li].y),
                                          to_tf32(pw[li].z), to_tf32(pw[li].w));
    }
    __syncthreads();

    for (int s = 0; s < nst; s++) {
        const int cur = s & 1;
        const bool more = (s + 1 < nst);
        if (more) {
            int kt = (s + 1) << 4;
#pragma unroll
            for (int li = 0; li < 2; li++) {
                int r = r0 + li * 64;
                pa[li] = loadA<MODE>(P, row0 + r, kt + c4 * 4);
                pw[li] = loadW<MODE>(P, col0 + r, kt + c4 * 4);
            }
        }

        // compute on buffer cur
#pragma unroll
        for (int ks = 0; ks < 2; ks++) {
            const int grp0 = ((2 * ks) ^ swz) << 2;
            const int grp1 = grp0 ^ 4;
            uint32_t af[4][4];
            uint32_t bf[4][2];
#pragma unroll
            for (int tmi = 0; tmi < 4; tmi++) {
                const uint32_t* A_ = &As[cur][(wm * 64 + tmi * 16 + g) * 16 + kq];
                af[tmi][0] = A_[grp0];
                af[tmi][1] = A_[128 + grp0];
                af[tmi][2] = A_[grp1];
                af[tmi][3] = A_[128 + grp1];
            }
#pragma unroll
            for (int tni = 0; tni < 4; tni++) {
                const uint32_t* B_ = &Bs[cur][(wn * 32 + tni * 8 + g) * 16 + kq];
                bf[tni][0] = B_[grp0];
                bf[tni][1] = B_[grp1];
            }
#pragma unroll
            for (int tmi = 0; tmi < 4; tmi++)
#pragma unroll
                for (int tni = 0; tni < 4; tni++)
                    mma_tf32(acc[tmi][tni], af[tmi], bf[tni]);
        }

        if (more) {
            const int nxt = cur ^ 1;
#pragma unroll
            for (int li = 0; li < 2; li++) {
                int r = r0 + li * 64;
                int off = r * 16 + ((c4 ^ ((r >> 1) & 3)) << 2);
                *(uint4*)&As[nxt][off] = make_uint4(to_tf32(pa[li].x), to_tf32(pa[li].y),
                                                    to_tf32(pa[li].z), to_tf32(pa[li].w));
                *(uint4*)&Bs[nxt][off] = make_uint4(to_tf32(pw[li].x), to_tf32(pw[li].y),
                                                    to_tf32(pw[li].z), to_tf32(pw[li].w));
            }
        }
        __syncthreads();
    }

    // epilogue: C-fragment c0,c1 -> (row=g, col=q*2, q*2+1); c2,c3 -> row+8
    const int q = lane & 3;
#pragma unroll
    for (int tmi = 0; tmi < 4; tmi++) {
        int rb = row0 + wm * 64 + tmi * 16;
#pragma unroll
        for (int h2 = 0; h2 < 2; h2++) {
            int gm = rb + g + h2 * 8;
#pragma unroll
            for (int tni = 0; tni < 4; tni++) {
                int gn = col0 + wn * 32 + tni * 8 + q * 2;
                float v0 = acc[tmi][tni][h2 * 2 + 0];
                float v1 = acc[tmi][tni][h2 * 2 + 1];
                if constexpr (MODE == 0) { v0 += P.b0[gn]; v1 += P.b0[gn + 1]; }
                else if constexpr (MODE == 1) {
                    v0 = fmaxf(v0 + P.b0[gn], 0.f);
                    v1 = fmaxf(v1 + P.b0[gn + 1], 0.f);
                } else if constexpr (MODE == 2) {
                    const float* rp = &P.res[(size_t)gm * P.N + gn];
                    v0 = v0 + P.b0[gn] + rp[0];
                    v1 = v1 + P.b0[gn + 1] + rp[1];
                } else if constexpr (MODE == 3) {
                    v0 = nonsat_f(v0 + P.b0[gn] + P.b1[gn] + P.b2[gn]);
                    v1 = nonsat_f(v1 + P.b0[gn + 1] + P.b1[gn + 1] + P.b2[gn + 1]);
                } else if constexpr (MODE == 4) {
                    /* raw */
                } else if constexpr (MODE == 5) {
                    const float* rp = &P.res[(size_t)gm * P.N + gn];
                    v0 = 0.5f * (rp[0] + v0);
                    v1 = 0.5f * (rp[1] + v1);
                } else if constexpr (MODE == 6) {
                    v0 = nonsat_f(v0 + P.b0[gn]);
                    v1 = nonsat_f(v1 + P.b0[gn + 1]);
                }
                *(float2*)&P.C[(size_t)gm * P.N + gn] = make_float2(v0, v1);
            }
        }
    }
}

// ---------------- LayerNorm (row of 512) ----------------
__global__ void __launch_bounds__(128) ln_kernel(const float* __restrict__ x,
                                                 const float* __restrict__ g,
                                                 const float* __restrict__ b,
                                                 float* __restrict__ out) {
    const int r = blockIdx.x, t = threadIdx.x;
    const float* row = x + (size_t)r * 512;
    float v0 = row[t], v1 = row[t + 128], v2 = row[t + 256], v3 = row[t + 384];
    __shared__ float sh[4];
    float s = v0 + v1 + v2 + v3;
#pragma unroll
    for (int o = 16; o; o >>= 1) s += __shfl_xor_sync(0xffffffffu, s, o);
    if ((t & 31) == 0) sh[t >> 5] = s;
    __syncthreads();
    float mean = (sh[0] + sh[1] + sh[2] + sh[3]) * (1.f / 512.f);
    __syncthreads();
    float d0 = v0 - mean, d1 = v1 - mean, d2 = v2 - mean, d3 = v3 - mean;
    float q = d0 * d0 + d1 * d1 + d2 * d2 + d3 * d3;
#pragma unroll
    for (int o = 16; o; o >>= 1) q += __shfl_xor_sync(0xffffffffu, q, o);
    if ((t & 31) == 0) sh[t >> 5] = q;
    __syncthreads();
    float var = (sh[0] + sh[1] + sh[2] + sh[3]) * (1.f / 512.f);
    float rstd = rsqrtf(var + 1e-5f);
    float* orow = out + (size_t)r * 512;
    orow[t]       = d0 * rstd * g[t]       + b[t];
    orow[t + 128] = d1 * rstd * g[t + 128] + b[t + 128];
    orow[t + 256] = d2 * rstd * g[t + 256] + b[t + 256];
    orow[t + 384] = d3 * rstd * g[t + 384] + b[t + 384];
}

// ---------------- Flash attention (64x64 tiles, causal) ----------------
__global__ void __launch_bounds__(256) attn_kernel(const float* __restrict__ qkv,
                                                   const unsigned char* __restrict__ kmask,
                                                   float* __restrict__ out) {
    extern __shared__ float sm[];
    float* Qt   = sm;                // [64 d][68] transposed, pre-scaled
    float* Kt   = Qt + 64 * 68;      // [64 d][68]
    float* Pt   = Kt + 64 * 68;      // scores/probs transposed [c][68 -> r]
    float* Vs   = Pt + 64 * 68;      // [c][68 -> d]
    float* mrow = Vs + 64 * 68;      // 64
    float* lrow = mrow + 64;         // 64
    float* rsc  = lrow + 64;         // 64
    float* kmf  = rsc + 64;          // 64

    const int tid = threadIdx.x;
    const int qt = blockIdx.x;       // 0..7
    const int bh = blockIdx.y;       // 0..127
    const int b = bh >> 3, h = bh & 7;
    const int ty = tid >> 4, tx = tid & 15;

#pragma unroll
    for (int li = 0; li < 4; li++) {
        int idx = tid + li * 256;
        int r = idx >> 4, d4 = idx & 15;
        float4 q = *(const float4*)&qkv[(size_t)((qt * 64 + r) * 16 + b) * 1536 + h * 64 + d4 * 4];
        Qt[(d4 * 4 + 0) * 68 + r] = q.x * 0.125f;
        Qt[(d4 * 4 + 1) * 68 + r] = q.y * 0.125f;
        Qt[(d4 * 4 + 2) * 68 + r] = q.z * 0.125f;
        Qt[(d4 * 4 + 3) * 68 + r] = q.w * 0.125f;
    }
    if (tid < 64) { mrow[tid] = -1e30f; lrow[tid] = 0.f; }
    float Oa[4][4];
#pragma unroll
    for (int i = 0; i < 4; i++)
#pragma unroll
        for (int j = 0; j < 4; j++) Oa[i][j] = 0.f;
    __syncthreads();

    for (int kt = 0; kt <= qt; kt++) {
#pragma unroll
        for (int li = 0; li < 4; li++) {
            int idx = tid + li * 256;
            int c = idx >> 4, d4 = idx & 15;
            size_t base = (size_t)((kt * 64 + c) * 16 + b) * 1536 + h * 64;
            float4 kv = *(const float4*)&qkv[base + 512 + d4 * 4];
            Kt[(d4 * 4 + 0) * 68 + c] = kv.x;
            Kt[(d4 * 4 + 1) * 68 + c] = kv.y;
            Kt[(d4 * 4 + 2) * 68 + c] = kv.z;
            Kt[(d4 * 4 + 3) * 68 + c] = kv.w;
            float4 vv = *(const float4*)&qkv[base + 1024 + d4 * 4];
            *(float4*)&Vs[c * 68 + d4 * 4] = vv;
        }
        if (tid < 64) kmf[tid] = kmask[b * 512 + kt * 64 + tid] ? -1e30f : 0.f;
        __syncthreads();

        float sc[4][4];
#pragma unroll
        for (int i = 0; i < 4; i++)
#pragma unroll
            for (int j = 0; j < 4; j++) sc[i][j] = 0.f;
#pragma unroll
        for (int d = 0; d < 64; d++) {
            float4 qa = *(const float4*)&Qt[d * 68 + ty * 4];
            float4 ka = *(const float4*)&Kt[d * 68 + tx * 4];
            float qr[4] = {qa.x, qa.y, qa.z, qa.w};
            float kr[4] = {ka.x, ka.y, ka.z, ka.w};
#pragma unroll
            for (int i = 0; i < 4; i++)
#pragma unroll
                for (int j = 0; j < 4; j++) sc[i][j] += qr[i] * kr[j];
        }
        const bool diag = (kt == qt);
#pragma unroll
        for (int j = 0; j < 4; j++) {
            int c = tx * 4 + j;
            float add = kmf[c];
            float vv[4];
#pragma unroll
            for (int i = 0; i < 4; i++) {
                int r = ty * 4 + i;
                float val = sc[i][j] + add;
                if (diag && c > r) val = -1e30f;
                vv[i] = val;
            }
            *(float4*)&Pt[c * 68 + ty * 4] = make_float4(vv[0], vv[1], vv[2], vv[3]);
        }
        __syncthreads();

        {
            int r = tid >> 2, q4 = tid & 3;
            float mx = -1e30f;
#pragma unroll
            for (int cc = 0; cc < 16; cc++) mx = fmaxf(mx, Pt[(q4 * 16 + cc) * 68 + r]);
            mx = fmaxf(mx, __shfl_xor_sync(0xffffffffu, mx, 1));
            mx = fmaxf(mx, __shfl_xor_sync(0xffffffffu, mx, 2));
            float mold = mrow[r];
            float mnew = fmaxf(mold, mx);
            float sum = 0.f;
#pragma unroll
            for (int cc = 0; cc < 16; cc++) {
                int c = q4 * 16 + cc;
                float p = __expf(Pt[c * 68 + r] - mnew);
                Pt[c * 68 + r] = p;
                sum += p;
            }
            sum += __shfl_xor_sync(0xffffffffu, sum, 1);
            sum += __shfl_xor_sync(0xffffffffu, sum, 2);
            if (q4 == 0) {
                float scale = __expf(mold - mnew);
                mrow[r] = mnew;
                lrow[r] = lrow[r] * scale + sum;
                rsc[r] = scale;
            }
        }
        __syncthreads();

#pragma unroll
        for (int i = 0; i < 4; i++) {
            float s0 = rsc[ty * 4 + i];
#pragma unroll
            for (int j = 0; j < 4; j++) Oa[i][j] *= s0;
        }
#pragma unroll
        for (int c = 0; c < 64; c++) {
            float4 pa = *(const float4*)&Pt[c * 68 + ty * 4];
            float4 va = *(const float4*)&Vs[c * 68 + tx * 4];
            float pr[4] = {pa.x, pa.y, pa.z, pa.w};
            float vr[4] = {va.x, va.y, va.z, va.w};
#pragma unroll
            for (int i = 0; i < 4; i++)
#pragma unroll
                for (int j = 0; j < 4; j++) Oa[i][j] += pr[i] * vr[j];
        }
        __syncthreads();
    }

#pragma unroll
    for (int i = 0; i < 4; i++) {
        int r = ty * 4 + i;
        float inv = __fdividef(1.f, lrow[r]);
        float4 o = make_float4(Oa[i][0] * inv, Oa[i][1] * inv, Oa[i][2] * inv, Oa[i][3] * inv);
        *(float4*)&out[(size_t)((qt * 64 + r) * 16 + b) * 512 + h * 64 + tx * 4] = o;
    }
}

// ---------------- softmax over 128 (mixture logits) ----------------
__global__ void __launch_bounds__(128) softmax128_kernel(float* __restrict__ lg) {
    const int r = blockIdx.x, t = threadIdx.x;
    float v = lg[(size_t)r * 128 + t];
    __shared__ float sh[4];
    float m = v;
#pragma unroll
    for (int o = 16; o; o >>= 1) m = fmaxf(m, __shfl_xor_sync(0xffffffffu, m, o));
    if ((t & 31) == 0) sh[t >> 5] = m;
    __syncthreads();
    m = fmaxf(fmaxf(sh[0], sh[1]), fmaxf(sh[2], sh[3]));
    float e = __expf(v - m);
    __syncthreads();
    float s = e;
#pragma unroll
    for (int o = 16; o; o >>= 1) s += __shfl_xor_sync(0xffffffffu, s, o);
    if ((t & 31) == 0) sh[t >> 5] = s;
    __syncthreads();
    s = sh[0] + sh[1] + sh[2] + sh[3];
    lg[(size_t)r * 128 + t] = e * __fdividef(1.f, s);
}

// ---------------- stack controls: softmax(hidden @ A_w^T + A_b) ----------------
__global__ void __launch_bounds__(128) controls_kernel(const float* __restrict__ hidden,
                                                       const float* __restrict__ Aw,
                                                       const float* __restrict__ Ab,
                                                       float* __restrict__ ctl) {
    const int r = blockIdx.x, t = threadIdx.x;
    const float* row = hidden + (size_t)r * 512;
    float s0 = 0.f, s1 = 0.f, s2 = 0.f;
#pragma unroll
    for (int i = 0; i < 4; i++) {
        int c = t + i * 128;
        float hv = row[c];
        s0 += hv * Aw[c];
        s1 += hv * Aw[512 + c];
        s2 += hv * Aw[1024 + c];
    }
    __shared__ float sh[3][4];
#pragma unroll
    for (int o = 16; o; o >>= 1) {
        s0 += __shfl_xor_sync(0xffffffffu, s0, o);
        s1 += __shfl_xor_sync(0xffffffffu, s1, o);
        s2 += __shfl_xor_sync(0xffffffffu, s2, o);
    }
    if ((t & 31) == 0) { sh[0][t >> 5] = s0; sh[1][t >> 5] = s1; sh[2][t >> 5] = s2; }
    __syncthreads();
    if (t == 0) {
        float c0 = sh[0][0] + sh[0][1] + sh[0][2] + sh[0][3] + Ab[0];
        float c1 = sh[1][0] + sh[1][1] + sh[1][2] + sh[1][3] + Ab[1];
        float c2 = sh[2][0] + sh[2][1] + sh[2][2] + sh[2][3] + Ab[2];
        float m = fmaxf(c0, fmaxf(c1, c2));
        float e0 = __expf(c0 - m), e1 = __expf(c1 - m), e2 = __expf(c2 - m);
        float inv = __fdividef(1.f, e0 + e1 + e2);
        ctl[r * 3 + 0] = e0 * inv;
        ctl[r * 3 + 1] = e1 * inv;
        ctl[r * 3 + 2] = e2 * inv;
    }
}

// ---------------- stack update ----------------
__global__ void __launch_bounds__(128) stack_kernel(const float* __restrict__ stack_prev,
                                                    const float* __restrict__ si,
                                                    const float* __restrict__ ctl,
                                                    float* __restrict__ out) {
    const int g = blockIdx.x;       // b*512+s
    const int w = threadIdx.x;      // 0..127
    const float* prev = stack_prev + (size_t)g * (SDEPTH * SWIDTH);
    float* o = out + (size_t)g * (SDEPTH * SWIDTH);
    const float cpush = ctl[g * 3 + 0];
    const float cpop  = ctl[g * 3 + 1];
    const float cnoop = ctl[g * 3 + 2];
    float pm1 = si[(size_t)g * 128 + w];   // push source at depth 0
    float p0 = prev[w];
#pragma unroll 4
    for (int d = 0; d < SDEPTH; d++) {
        float p1 = (d < SDEPTH - 1) ? prev[(d + 1) * SWIDTH + w] : 0.f;
        o[d * SWIDTH + w] = cnoop * p0 + cpush * pm1 + cpop * p1;
        pm1 = p0;
        p0 = p1;
    }
}

// ---------------- host ----------------
template<int MODE>
static void launch_gemm(const GemmArgs& P) {
    dim3 grid(P.N / 128, P.M / 128);
    gemm_tc<MODE><<<grid, 256>>>(P);
}

extern "C" void kernel_launch(void* const* d_in, const int* in_sizes, int n_in,
                              void* d_out, int out_size) {
    const float* x_in        = (const float*)d_in[0];
    const float* hidden_prev = (const float*)d_in[1];
    const float* stack_prev  = (const float*)d_in[2];
    const unsigned char* k_mask = (const unsigned char*)d_in[3];
    const float* in_proj_w  = (const float*)d_in[4];
    const float* in_proj_b  = (const float*)d_in[5];
    const float* out_proj_w = (const float*)d_in[6];
    const float* out_proj_b = (const float*)d_in[7];
    const float* ln1_g = (const float*)d_in[8];
    const float* ln1_b = (const float*)d_in[9];
    const float* ln2_g = (const float*)d_in[10];
    const float* ln2_b = (const float*)d_in[11];
    const float* ff_w1 = (const float*)d_in[12];
    const float* ff_b1 = (const float*)d_in[13];
    const float* ff_w2 = (const float*)d_in[14];
    const float* ff_b2 = (const float*)d_in[15];
    const float* W_w = (const float*)d_in[16];
    const float* W_b = (const float*)d_in[17];
    const float* R_w = (const float*)d_in[18];
    const float* R_b = (const float*)d_in[19];
    const float* P_w = (const float*)d_in[20];
    const float* P_b = (const float*)d_in[21];
    const float* V_w = (const float*)d_in[22];
    const float* U_w = (const float*)d_in[23];
    const float* A_w = (const float*)d_in[24];
    const float* A_b = (const float*)d_in[25];
    const float* D_w = (const float*)d_in[26];
    const float* D_b = (const float*)d_in[27];

    float *h1, *qkvb, *attb, *xb, *lg, *si, *ctl, *h2, *f1;
    cudaGetSymbolAddress((void**)&h1,  g_h1);
    cudaGetSymbolAddress((void**)&qkvb, g_qkv);
    cudaGetSymbolAddress((void**)&attb, g_att);
    cudaGetSymbolAddress((void**)&xb,  g_x);
    cudaGetSymbolAddress((void**)&lg,  g_lg);
    cudaGetSymbolAddress((void**)&si,  g_si);
    cudaGetSymbolAddress((void**)&ctl, g_ctl);
    cudaGetSymbolAddress((void**)&h2,  g_h2);
    cudaGetSymbolAddress((void**)&f1,  g_f1);

    float* out_x      = (float*)d_out;
    float* out_hidden = out_x + (size_t)SB * EMB;
    float* out_stack  = out_hidden + (size_t)SB * EMB;

    const int ATTN_SMEM = (4 * 64 * 68 + 4 * 64) * (int)sizeof(float);
    cudaFuncSetAttribute(attn_kernel, cudaFuncAttributeMaxDynamicSharedMemorySize, ATTN_SMEM);

    // 1. LN1
    ln_kernel<<<SB, 128>>>(x_in, ln1_g, ln1_b, h1);

    // 2. QKV projection
    {
        GemmArgs P{};
        P.A0 = h1; P.W0 = in_proj_w; P.b0 = in_proj_b; P.C = qkvb;
        P.M = SB; P.N = 3 * EMB; P.K = EMB;
        launch_gemm<0>(P);
    }

    // 3. Attention (causal flash)
    attn_kernel<<<dim3(SEQ / 64, BATCH * NHEADS), 256, ATTN_SMEM>>>(qkvb, k_mask, attb);

    // 4. Output projection + residual -> x
    {
        GemmArgs P{};
        P.A0 = attb; P.W0 = out_proj_w; P.b0 = out_proj_b; P.res = x_in; P.C = xb;
        P.M = SB; P.N = EMB; P.K = EMB;
        launch_gemm<2>(P);
    }

    // 5. hidden = nonsat(xb@W^T + hprev@R^T + stack_top@P^T + biases)
    {
        GemmArgs P{};
        P.A0 = xb; P.A1 = hidden_prev; P.A2 = stack_prev;
        P.W0 = W_w; P.W1 = R_w; P.W2 = P_w;
        P.b0 = W_b; P.b1 = R_b; P.b2 = P_b;
        P.C = out_hidden;
        P.M = SB; P.N = EMB; P.K = 1152;
        launch_gemm<3>(P);
    }

    // 6. logits = [x | hidden^T] @ V_w^T
    {
        GemmArgs P{};
        P.A0 = xb; P.A1 = out_hidden; P.W0 = V_w; P.C = lg;
        P.M = SB; P.N = DSS; P.K = 1024;
        launch_gemm<4>(P);
    }

    // 7. softmax over 128
    softmax128_kernel<<<SB, 128>>>(lg);

    // 8. x = 0.5*(x + p @ U_w^T)
    {
        GemmArgs P{};
        P.A0 = lg; P.W0 = U_w; P.res = xb; P.C = xb;
        P.M = SB; P.N = EMB; P.K = DSS;
        launch_gemm<5>(P);
    }

    // 9. stack_inp = nonsat(hidden @ D_w^T + D_b)
    {
        GemmArgs P{};
        P.A0 = out_hidden; P.W0 = D_w; P.b0 = D_b; P.C = si;
        P.M = SB; P.N = SWIDTH; P.K = EMB;
        launch_gemm<6>(P);
    }

    // 10. controls
    controls_kernel<<<SB, 128>>>(out_hidden, A_w, A_b, ctl);

    // 11. stack update
    stack_kernel<<<SB, 128>>>(stack_prev, si, ctl, out_stack);

    // 12. LN2
    ln_kernel<<<SB, 128>>>(xb, ln2_g, ln2_b, h2);

    // 13. FF1 (relu)
    {
        GemmArgs P{};
        P.A0 = h2; P.W0 = ff_w1; P.b0 = ff_b1; P.C = f1;
        P.M = SB; P.N = DFF; P.K = EMB;
        launch_gemm<1>(P);
    }

    // 14. FF2 + residual -> out_x
    {
        GemmArgs P{};
        P.A0 = f1; P.W0 = ff_w2; P.b0 = ff_b2; P.res = xb; P.C = out_x;
        P.M = SB; P.N = EMB; P.K = DFF;
        launch_gemm<2>(P);
    }
}

// round 10
// speedup vs baseline: 1.5662x; 1.1812x over previous
#include <cuda_runtime.h>
#include <cuda_bf16.h>
#include <cstdint>

// Problem dims
#define SEQ 512
#define BATCH 16
#define EMB 512
#define SB 8192           // SEQ*BATCH rows
#define DFF 2048
#define DSS 128
#define SDEPTH 48
#define SWIDTH 128
#define NHEADS 8
#define HDIM 64

// ---------------- scratch (device globals; no allocation) ----------------
__device__ float g_h1 [SB * EMB];
__device__ float g_qkv[SB * 3 * EMB];
__device__ float g_att[SB * EMB];
__device__ float g_x  [SB * EMB];
__device__ float g_xt [SB * EMB];      // tf32-rounded copy of x
__device__ float g_ht [SB * EMB];      // tf32-rounded copy of hidden
__device__ float g_hpt[SB * EMB];      // tf32-rounded hidden_prev
__device__ float g_stt[SB * SWIDTH];   // tf32-rounded stack top slice
__device__ float g_lg [SB * DSS];
__device__ float g_si [SB * SWIDTH];
__device__ float g_ctl[SB * 3];
__device__ float g_h2 [SB * EMB];
__device__ float g_f1 [SB * DFF];
__device__ float g_wt [3997696];       // tf32-rounded weights pool

// ---------------- helpers ----------------
__device__ __forceinline__ float nonsat_f(float x) {
    // Newton for y^3/3 + y = x ; reference's step() IS the Newton update.
    float y = x;
#pragma unroll
    for (int i = 0; i < 20; i++) {
        float y2 = y * y;
        y = __fdividef(0.6666666666666666f * y2 * y + x, y2 + 1.0f);
    }
    return y;
}

__device__ __forceinline__ uint32_t to_tf32(float x) {
    uint32_t r;
    asm("cvt.rna.tf32.f32 %0, %1;" : "=r"(r) : "f"(x));
    return r;
}
__device__ __forceinline__ float rtf(float x) { return __uint_as_float(to_tf32(x)); }

__device__ __forceinline__ void mma_tf32(float (&c)[4], const uint32_t (&a)[4], const uint32_t (&b)[2]) {
    asm volatile(
        "mma.sync.aligned.m16n8k8.row.col.f32.tf32.tf32.f32 "
        "{%0,%1,%2,%3},{%4,%5,%6,%7},{%8,%9},{%0,%1,%2,%3};"
        : "+f"(c[0]), "+f"(c[1]), "+f"(c[2]), "+f"(c[3])
        : "r"(a[0]), "r"(a[1]), "r"(a[2]), "r"(a[3]), "r"(b[0]), "r"(b[1]));
}

__device__ __forceinline__ void cp16(uint32_t dst, const float* src) {
    asm volatile("cp.async.cg.shared.global [%0], [%1], 16;" :: "r"(dst), "l"(src));
}
#define CP_COMMIT() asm volatile("cp.async.commit_group;")
#define CP_WAIT1()  asm volatile("cp.async.wait_group 1;")

// ---------------- pre-round pass: tf32-round tensors into scratch ----------------
struct RoundEntry { const float* src; float* dst; int n; int shift; int mask; int stride; };
struct RoundArgs { RoundEntry e[12]; };

__global__ void __launch_bounds__(256) round_multi(RoundArgs A) {
    const int gs = gridDim.x * blockDim.x;
    const int t0 = blockIdx.x * blockDim.x + threadIdx.x;
#pragma unroll 1
    for (int i = 0; i < 12; i++) {
        const RoundEntry E = A.e[i];
        for (int idx = t0; idx < E.n; idx += gs) {
            int row = idx >> E.shift;
            int col = idx & E.mask;
            E.dst[idx] = rtf(E.src[(size_t)row * E.stride + col]);
        }
    }
}

// ---------------- GEMM: C[M,N] = A[M,K] @ W[N,K]^T + epilogue ----------------
struct GemmArgs {
    const float* A0; const float* A1; const float* A2;
    const float* W0; const float* W1; const float* W2;
    const float* b0; const float* b1; const float* b2;
    const float* res;
    float* C;
    float* C2;     // optional tf32-rounded twin output
    int M, N, K;
};

// MODE: 0=+bias  1=+bias,relu,round  2=+bias+res(+C2 round)  3=hidden(3src,+3bias,nonsat,+C2)
//       4=logits(2src,nobias)  5=mix(res: 0.5*(res+acc))  6=+bias,nonsat
template<int MODE>
__device__ __forceinline__ const float* addrA(const GemmArgs& P, int grow, int gk) {
    if constexpr (MODE == 3) {
        if (gk < 512) {
            // grow = b*512+s (hidden order); x lives in (s,b) order
            int xr = ((grow & 511) << 4) + (grow >> 9);
            return &P.A0[(size_t)xr * 512 + gk];
        } else if (gk < 1024) {
            return &P.A1[(size_t)grow * 512 + (gk - 512)];
        } else {
            return &P.A2[(size_t)grow * 128 + (gk - 1024)];   // pre-extracted stack top
        }
    } else if constexpr (MODE == 4) {
        if (gk < 512) return &P.A0[(size_t)grow * 512 + gk];
        int hr = ((grow & 15) << 9) + (grow >> 4);
        return &P.A1[(size_t)hr * 512 + (gk - 512)];
    } else {
        return &P.A0[(size_t)grow * (size_t)P.K + gk];
    }
}

template<int MODE>
__device__ __forceinline__ const float* addrW(const GemmArgs& P, int n, int gk) {
    if constexpr (MODE == 3) {
        if (gk < 512)       return &P.W0[(size_t)n * 512 + gk];
        else if (gk < 1024) return &P.W1[(size_t)n * 512 + (gk - 512)];
        else                return &P.W2[(size_t)n * 128 + (gk - 1024)];
    } else {
        return &P.W0[(size_t)n * (size_t)P.K + gk];
    }
}

// 128x128x16 tile, 256 threads = 8 warps (2x4), 3-stage cp.async ring.
// Smem layout: [row][16 k], crosswise swizzle: float4-group g' = g ^ ((row>>1)&3).
// All GEMM operands are pre-rounded tf32-exact fp32 -> raw bits feed mma.tf32 exactly.
template<int MODE>
__global__ void __launch_bounds__(256) gemm_tc(GemmArgs P) {
    __shared__ uint32_t As[3][2048];
    __shared__ uint32_t Bs[3][2048];

    const int tid  = threadIdx.x;
    const int lane = tid & 31;
    const int warp = tid >> 5;
    const int wm = warp >> 2;           // 0..1
    const int wn = warp & 3;            // 0..3
    const int bn = blockIdx.x, bm = blockIdx.y;
    const int row0 = bm * 128, col0 = bn * 128;

    const int r0 = tid >> 2;            // 0..63 (li adds 64)
    const int c4 = tid & 3;

    const int g  = lane >> 2;
    const int kq = lane & 3;
    const int swz = (g >> 1) & 3;

    const int nst = P.K >> 4;

    int offs[2];
    uint32_t rA[2], rB[2];              // per-li row indices for global addressing
#pragma unroll
    for (int li = 0; li < 2; li++) {
        int r = r0 + li * 64;
        offs[li] = r * 16 + ((c4 ^ ((r >> 1) & 3)) << 2);
        rA[li] = row0 + r;
        rB[li] = col0 + r;
    }

    auto issue = [&](int s, int b) {
        int kt = (s << 4) + c4 * 4;
#pragma unroll
        for (int li = 0; li < 2; li++) {
            cp16((uint32_t)__cvta_generic_to_shared(&As[b][offs[li]]), addrA<MODE>(P, rA[li], kt));
            cp16((uint32_t)__cvta_generic_to_shared(&Bs[b][offs[li]]), addrW<MODE>(P, rB[li], kt));
        }
    };

    issue(0, 0);
    CP_COMMIT();
    if (nst > 1) issue(1, 1);
    CP_COMMIT();

    float acc[4][4][4];
#pragma unroll
    for (int i = 0; i < 4; i++)
#pragma unroll
        for (int j = 0; j < 4; j++)
#pragma unroll
            for (int e = 0; e < 4; e++) acc[i][j][e] = 0.f;

    int buf = 0, pbuf = 2;
#pragma unroll 1
    for (int s = 0; s < nst; s++) {
        CP_WAIT1();
        __syncthreads();
        if (s + 2 < nst) issue(s + 2, pbuf);
        CP_COMMIT();

#pragma unroll
        for (int ks = 0; ks < 2; ks++) {
            const int grp0 = ((2 * ks) ^ swz) << 2;
            const int grp1 = grp0 ^ 4;
            uint32_t af[4][4];
            uint32_t bf[4][2];
#pragma unroll
            for (int tmi = 0; tmi < 4; tmi++) {
                const uint32_t* A_ = &As[buf][(wm * 64 + tmi * 16 + g) * 16 + kq];
                af[tmi][0] = A_[grp0];
                af[tmi][1] = A_[128 + grp0];
                af[tmi][2] = A_[grp1];
                af[tmi][3] = A_[128 + grp1];
            }
#pragma unroll
            for (int tni = 0; tni < 4; tni++) {
                const uint32_t* B_ = &Bs[buf][(wn * 32 + tni * 8 + g) * 16 + kq];
                bf[tni][0] = B_[grp0];
                bf[tni][1] = B_[grp1];
            }
#pragma unroll
            for (int tmi = 0; tmi < 4; tmi++)
#pragma unroll
                for (int tni = 0; tni < 4; tni++)
                    mma_tf32(acc[tmi][tni], af[tmi], bf[tni]);
        }
        buf  = (buf == 2)  ? 0 : buf + 1;
        pbuf = (pbuf == 2) ? 0 : pbuf + 1;
    }

    // epilogue: C-fragment c0,c1 -> (row=g, col=q*2, q*2+1); c2,c3 -> row+8
    const int q = lane & 3;
#pragma unroll
    for (int tmi = 0; tmi < 4; tmi++) {
        int rb = row0 + wm * 64 + tmi * 16;
#pragma unroll
        for (int h2 = 0; h2 < 2; h2++) {
            int gm = rb + g + h2 * 8;
#pragma unroll
            for (int tni = 0; tni < 4; tni++) {
                int gn = col0 + wn * 32 + tni * 8 + q * 2;
                float v0 = acc[tmi][tni][h2 * 2 + 0];
                float v1 = acc[tmi][tni][h2 * 2 + 1];
                if constexpr (MODE == 0) { v0 += P.b0[gn]; v1 += P.b0[gn + 1]; }
                else if constexpr (MODE == 1) {
                    v0 = rtf(fmaxf(v0 + P.b0[gn], 0.f));
                    v1 = rtf(fmaxf(v1 + P.b0[gn + 1], 0.f));
                } else if constexpr (MODE == 2) {
                    const float* rp = &P.res[(size_t)gm * P.N + gn];
                    v0 = v0 + P.b0[gn] + rp[0];
                    v1 = v1 + P.b0[gn + 1] + rp[1];
                } else if constexpr (MODE == 3) {
                    v0 = nonsat_f(v0 + P.b0[gn] + P.b1[gn] + P.b2[gn]);
                    v1 = nonsat_f(v1 + P.b0[gn + 1] + P.b1[gn + 1] + P.b2[gn + 1]);
                } else if constexpr (MODE == 4) {
                    /* raw */
                } else if constexpr (MODE == 5) {
                    const float* rp = &P.res[(size_t)gm * P.N + gn];
                    v0 = 0.5f * (rp[0] + v0);
                    v1 = 0.5f * (rp[1] + v1);
                } else if constexpr (MODE == 6) {
                    v0 = nonsat_f(v0 + P.b0[gn]);
                    v1 = nonsat_f(v1 + P.b0[gn + 1]);
                }
                *(float2*)&P.C[(size_t)gm * P.N + gn] = make_float2(v0, v1);
                if constexpr (MODE == 2 || MODE == 3) {
                    if (P.C2)
                        *(float2*)&P.C2[(size_t)gm * P.N + gn] = make_float2(rtf(v0), rtf(v1));
                }
            }
        }
    }
}

// ---------------- LayerNorm (row of 512), output tf32-rounded ----------------
__global__ void __launch_bounds__(128) ln_kernel(const float* __restrict__ x,
                                                 const float* __restrict__ g,
                                                 const float* __restrict__ b,
                                                 float* __restrict__ out) {
    const int r = blockIdx.x, t = threadIdx.x;
    const float* row = x + (size_t)r * 512;
    float v0 = row[t], v1 = row[t + 128], v2 = row[t + 256], v3 = row[t + 384];
    __shared__ float sh[4];
    float s = v0 + v1 + v2 + v3;
#pragma unroll
    for (int o = 16; o; o >>= 1) s += __shfl_xor_sync(0xffffffffu, s, o);
    if ((t & 31) == 0) sh[t >> 5] = s;
    __syncthreads();
    float mean = (sh[0] + sh[1] + sh[2] + sh[3]) * (1.f / 512.f);
    __syncthreads();
    float d0 = v0 - mean, d1 = v1 - mean, d2 = v2 - mean, d3 = v3 - mean;
    float q = d0 * d0 + d1 * d1 + d2 * d2 + d3 * d3;
#pragma unroll
    for (int o = 16; o; o >>= 1) q += __shfl_xor_sync(0xffffffffu, q, o);
    if ((t & 31) == 0) sh[t >> 5] = q;
    __syncthreads();
    float var = (sh[0] + sh[1] + sh[2] + sh[3]) * (1.f / 512.f);
    float rstd = rsqrtf(var + 1e-5f);
    float* orow = out + (size_t)r * 512;
    orow[t]       = rtf(d0 * rstd * g[t]       + b[t]);
    orow[t + 128] = rtf(d1 * rstd * g[t + 128] + b[t + 128]);
    orow[t + 256] = rtf(d2 * rstd * g[t + 256] + b[t + 256]);
    orow[t + 384] = rtf(d3 * rstd * g[t + 384] + b[t + 384]);
}

// ---------------- Flash attention (64x64 tiles, causal); output tf32-rounded ----
__global__ void __launch_bounds__(256) attn_kernel(const float* __restrict__ qkv,
                                                   const unsigned char* __restrict__ kmask,
                                                   float* __restrict__ out) {
    extern __shared__ float sm[];
    float* Qt   = sm;                // [64 d][68] transposed, pre-scaled
    float* Kt   = Qt + 64 * 68;      // [64 d][68]
    float* Pt   = Kt + 64 * 68;      // scores/probs transposed [c][68 -> r]
    float* Vs   = Pt + 64 * 68;      // [c][68 -> d]
    float* mrow = Vs + 64 * 68;      // 64
    float* lrow = mrow + 64;         // 64
    float* rsc  = lrow + 64;         // 64
    float* kmf  = rsc + 64;          // 64

    const int tid = threadIdx.x;
    const int qt = blockIdx.x;       // 0..7
    const int bh = blockIdx.y;       // 0..127
    const int b = bh >> 3, h = bh & 7;
    const int ty = tid >> 4, tx = tid & 15;

#pragma unroll
    for (int li = 0; li < 4; li++) {
        int idx = tid + li * 256;
        int r = idx >> 4, d4 = idx & 15;
        float4 q = *(const float4*)&qkv[(size_t)((qt * 64 + r) * 16 + b) * 1536 + h * 64 + d4 * 4];
        Qt[(d4 * 4 + 0) * 68 + r] = q.x * 0.125f;
        Qt[(d4 * 4 + 1) * 68 + r] = q.y * 0.125f;
        Qt[(d4 * 4 + 2) * 68 + r] = q.z * 0.125f;
        Qt[(d4 * 4 + 3) * 68 + r] = q.w * 0.125f;
    }
    if (tid < 64) { mrow[tid] = -1e30f; lrow[tid] = 0.f; }
    float Oa[4][4];
#pragma unroll
    for (int i = 0; i < 4; i++)
#pragma unroll
        for (int j = 0; j < 4; j++) Oa[i][j] = 0.f;
    __syncthreads();

    for (int kt = 0; kt <= qt; kt++) {
#pragma unroll
        for (int li = 0; li < 4; li++) {
            int idx = tid + li * 256;
            int c = idx >> 4, d4 = idx & 15;
            size_t base = (size_t)((kt * 64 + c) * 16 + b) * 1536 + h * 64;
            float4 kv = *(const float4*)&qkv[base + 512 + d4 * 4];
            Kt[(d4 * 4 + 0) * 68 + c] = kv.x;
            Kt[(d4 * 4 + 1) * 68 + c] = kv.y;
            Kt[(d4 * 4 + 2) * 68 + c] = kv.z;
            Kt[(d4 * 4 + 3) * 68 + c] = kv.w;
            float4 vv = *(const float4*)&qkv[base + 1024 + d4 * 4];
            *(float4*)&Vs[c * 68 + d4 * 4] = vv;
        }
        if (tid < 64) kmf[tid] = kmask[b * 512 + kt * 64 + tid] ? -1e30f : 0.f;
        __syncthreads();

        float sc[4][4];
#pragma unroll
        for (int i = 0; i < 4; i++)
#pragma unroll
            for (int j = 0; j < 4; j++) sc[i][j] = 0.f;
#pragma unroll
        for (int d = 0; d < 64; d++) {
            float4 qa = *(const float4*)&Qt[d * 68 + ty * 4];
            float4 ka = *(const float4*)&Kt[d * 68 + tx * 4];
            float qr[4] = {qa.x, qa.y, qa.z, qa.w};
            float kr[4] = {ka.x, ka.y, ka.z, ka.w};
#pragma unroll
            for (int i = 0; i < 4; i++)
#pragma unroll
                for (int j = 0; j < 4; j++) sc[i][j] += qr[i] * kr[j];
        }
        const bool diag = (kt == qt);
#pragma unroll
        for (int j = 0; j < 4; j++) {
            int c = tx * 4 + j;
            float add = kmf[c];
            float vv[4];
#pragma unroll
            for (int i = 0; i < 4; i++) {
                int r = ty * 4 + i;
                float val = sc[i][j] + add;
                if (diag && c > r) val = -1e30f;
                vv[i] = val;
            }
            *(float4*)&Pt[c * 68 + ty * 4] = make_float4(vv[0], vv[1], vv[2], vv[3]);
        }
        __syncthreads();

        {
            int r = tid >> 2, q4 = tid & 3;
            float mx = -1e30f;
#pragma unroll
            for (int cc = 0; cc < 16; cc++) mx = fmaxf(mx, Pt[(q4 * 16 + cc) * 68 + r]);
            mx = fmaxf(mx, __shfl_xor_sync(0xffffffffu, mx, 1));
            mx = fmaxf(mx, __shfl_xor_sync(0xffffffffu, mx, 2));
            float mold = mrow[r];
            float mnew = fmaxf(mold, mx);
            float sum = 0.f;
#pragma unroll
            for (int cc = 0; cc < 16; cc++) {
                int c = q4 * 16 + cc;
                float p = __expf(Pt[c * 68 + r] - mnew);
                Pt[c * 68 + r] = p;
                sum += p;
            }
            sum += __shfl_xor_sync(0xffffffffu, sum, 1);
            sum += __shfl_xor_sync(0xffffffffu, sum, 2);
            if (q4 == 0) {
                float scale = __expf(mold - mnew);
                mrow[r] = mnew;
                lrow[r] = lrow[r] * scale + sum;
                rsc[r] = scale;
            }
        }
        __syncthreads();

#pragma unroll
        for (int i = 0; i < 4; i++) {
            float s0 = rsc[ty * 4 + i];
#pragma unroll
            for (int j = 0; j < 4; j++) Oa[i][j] *= s0;
        }
#pragma unroll
        for (int c = 0; c < 64; c++) {
            float4 pa = *(const float4*)&Pt[c * 68 + ty * 4];
            float4 va = *(const float4*)&Vs[c * 68 + tx * 4];
            float pr[4] = {pa.x, pa.y, pa.z, pa.w};
            float vr[4] = {va.x, va.y, va.z, va.w};
#pragma unroll
            for (int i = 0; i < 4; i++)
#pragma unroll
                for (int j = 0; j < 4; j++) Oa[i][j] += pr[i] * vr[j];
        }
        __syncthreads();
    }

#pragma unroll
    for (int i = 0; i < 4; i++) {
        int r = ty * 4 + i;
        float inv = __fdividef(1.f, lrow[r]);
        float4 o = make_float4(rtf(Oa[i][0] * inv), rtf(Oa[i][1] * inv),
                               rtf(Oa[i][2] * inv), rtf(Oa[i][3] * inv));
        *(float4*)&out[(size_t)((qt * 64 + r) * 16 + b) * 512 + h * 64 + tx * 4] = o;
    }
}

// ---------------- softmax over 128 (mixture logits), output tf32-rounded -------
__global__ void __launch_bounds__(128) softmax128_kernel(float* __restrict__ lg) {
    const int r = blockIdx.x, t = threadIdx.x;
    float v = lg[(size_t)r * 128 + t];
    __shared__ float sh[4];
    float m = v;
#pragma unroll
    for (int o = 16; o; o >>= 1) m = fmaxf(m, __shfl_xor_sync(0xffffffffu, m, o));
    if ((t & 31) == 0) sh[t >> 5] = m;
    __syncthreads();
    m = fmaxf(fmaxf(sh[0], sh[1]), fmaxf(sh[2], sh[3]));
    float e = __expf(v - m);
    __syncthreads();
    float s = e;
#pragma unroll
    for (int o = 16; o; o >>= 1) s += __shfl_xor_sync(0xffffffffu, s, o);
    if ((t & 31) == 0) sh[t >> 5] = s;
    __syncthreads();
    s = sh[0] + sh[1] + sh[2] + sh[3];
    lg[(size_t)r * 128 + t] = rtf(e * __fdividef(1.f, s));
}

// ---------------- stack controls: softmax(hidden @ A_w^T + A_b) ----------------
__global__ void __launch_bounds__(128) controls_kernel(const float* __restrict__ hidden,
                                                       const float* __restrict__ Aw,
                                                       const float* __restrict__ Ab,
                                                       float* __restrict__ ctl) {
    const int r = blockIdx.x, t = threadIdx.x;
    const float* row = hidden + (size_t)r * 512;
    float s0 = 0.f, s1 = 0.f, s2 = 0.f;
#pragma unroll
    for (int i = 0; i < 4; i++) {
        int c = t + i * 128;
        float hv = row[c];
        s0 += hv * Aw[c];
        s1 += hv * Aw[512 + c];
        s2 += hv * Aw[1024 + c];
    }
    __shared__ float sh[3][4];
#pragma unroll
    for (int o = 16; o; o >>= 1) {
        s0 += __shfl_xor_sync(0xffffffffu, s0, o);
        s1 += __shfl_xor_sync(0xffffffffu, s1, o);
        s2 += __shfl_xor_sync(0xffffffffu, s2, o);
    }
    if ((t & 31) == 0) { sh[0][t >> 5] = s0; sh[1][t >> 5] = s1; sh[2][t >> 5] = s2; }
    __syncthreads();
    if (t == 0) {
        float c0 = sh[0][0] + sh[0][1] + sh[0][2] + sh[0][3] + Ab[0];
        float c1 = sh[1][0] + sh[1][1] + sh[1][2] + sh[1][3] + Ab[1];
        float c2 = sh[2][0] + sh[2][1] + sh[2][2] + sh[2][3] + Ab[2];
        float m = fmaxf(c0, fmaxf(c1, c2));
        float e0 = __expf(c0 - m), e1 = __expf(c1 - m), e2 = __expf(c2 - m);
        float inv = __fdividef(1.f, e0 + e1 + e2);
        ctl[r * 3 + 0] = e0 * inv;
        ctl[r * 3 + 1] = e1 * inv;
        ctl[r * 3 + 2] = e2 * inv;
    }
}

// ---------------- stack update ----------------
__global__ void __launch_bounds__(128) stack_kernel(const float* __restrict__ stack_prev,
                                                    const float* __restrict__ si,
                                                    const float* __restrict__ ctl,
                                                    float* __restrict__ out) {
    const int g = blockIdx.x;       // b*512+s
    const int w = threadIdx.x;      // 0..127
    const float* prev = stack_prev + (size_t)g * (SDEPTH * SWIDTH);
    float* o = out + (size_t)g * (SDEPTH * SWIDTH);
    const float cpush = ctl[g * 3 + 0];
    const float cpop  = ctl[g * 3 + 1];
    const float cnoop = ctl[g * 3 + 2];
    float pm1 = si[(size_t)g * 128 + w];   // push source at depth 0
    float p0 = prev[w];
#pragma unroll 4
    for (int d = 0; d < SDEPTH; d++) {
        float p1 = (d < SDEPTH - 1) ? prev[(d + 1) * SWIDTH + w] : 0.f;
        o[d * SWIDTH + w] = cnoop * p0 + cpush * pm1 + cpop * p1;
        pm1 = p0;
        p0 = p1;
    }
}

// ---------------- host ----------------
template<int MODE>
static void launch_gemm(const GemmArgs& P) {
    dim3 grid(P.N / 128, P.M / 128);
    gemm_tc<MODE><<<grid, 256>>>(P);
}

extern "C" void kernel_launch(void* const* d_in, const int* in_sizes, int n_in,
                              void* d_out, int out_size) {
    const float* x_in        = (const float*)d_in[0];
    const float* hidden_prev = (const float*)d_in[1];
    const float* stack_prev  = (const float*)d_in[2];
    const unsigned char* k_mask = (const unsigned char*)d_in[3];
    const float* in_proj_w  = (const float*)d_in[4];
    const float* in_proj_b  = (const float*)d_in[5];
    const float* out_proj_w = (const float*)d_in[6];
    const float* out_proj_b = (const float*)d_in[7];
    const float* ln1_g = (const float*)d_in[8];
    const float* ln1_b = (const float*)d_in[9];
    const float* ln2_g = (const float*)d_in[10];
    const float* ln2_b = (const float*)d_in[11];
    const float* ff_w1 = (const float*)d_in[12];
    const float* ff_b1 = (const float*)d_in[13];
    const float* ff_w2 = (const float*)d_in[14];
    const float* ff_b2 = (const float*)d_in[15];
    const float* W_w = (const float*)d_in[16];
    const float* W_b = (const float*)d_in[17];
    const float* R_w = (const float*)d_in[18];
    const float* R_b = (const float*)d_in[19];
    const float* P_w = (const float*)d_in[20];
    const float* P_b = (const float*)d_in[21];
    const float* V_w = (const float*)d_in[22];
    const float* U_w = (const float*)d_in[23];
    const float* A_w = (const float*)d_in[24];
    const float* A_b = (const float*)d_in[25];
    const float* D_w = (const float*)d_in[26];
    const float* D_b = (const float*)d_in[27];

    float *h1, *qkvb, *attb, *xb, *xt, *ht, *hpt, *stt, *lg, *si, *ctl, *h2, *f1, *wt;
    cudaGetSymbolAddress((void**)&h1,  g_h1);
    cudaGetSymbolAddress((void**)&qkvb, g_qkv);
    cudaGetSymbolAddress((void**)&attb, g_att);
    cudaGetSymbolAddress((void**)&xb,  g_x);
    cudaGetSymbolAddress((void**)&xt,  g_xt);
    cudaGetSymbolAddress((void**)&ht,  g_ht);
    cudaGetSymbolAddress((void**)&hpt, g_hpt);
    cudaGetSymbolAddress((void**)&stt, g_stt);
    cudaGetSymbolAddress((void**)&lg,  g_lg);
    cudaGetSymbolAddress((void**)&si,  g_si);
    cudaGetSymbolAddress((void**)&ctl, g_ctl);
    cudaGetSymbolAddress((void**)&h2,  g_h2);
    cudaGetSymbolAddress((void**)&f1,  g_f1);
    cudaGetSymbolAddress((void**)&wt,  g_wt);

    // tf32-rounded weight pool offsets
    float* t_inproj = wt + 0;
    float* t_outprj = wt + 786432;
    float* t_Ww     = wt + 1048576;
    float* t_Rw     = wt + 1310720;
    float* t_Pw     = wt + 1572864;
    float* t_Vw     = wt + 1638400;
    float* t_Uw     = wt + 1769472;
    float* t_Dw     = wt + 1835008;
    float* t_ff1    = wt + 1900544;
    float* t_ff2    = wt + 2949120;

    float* out_x      = (float*)d_out;
    float* out_hidden = out_x + (size_t)SB * EMB;
    float* out_stack  = out_hidden + (size_t)SB * EMB;

    const int ATTN_SMEM = (4 * 64 * 68 + 4 * 64) * (int)sizeof(float);
    cudaFuncSetAttribute(attn_kernel, cudaFuncAttributeMaxDynamicSharedMemorySize, ATTN_SMEM);

    // 0. pre-round weights + hidden_prev + stack top to tf32-exact fp32
    {
        const int FM = 0x3FFFFFFF;
        RoundArgs RA{};
        RA.e[0]  = {in_proj_w,  t_inproj, 786432,  30, FM, 0};
        RA.e[1]  = {out_proj_w, t_outprj, 262144,  30, FM, 0};
        RA.e[2]  = {W_w,        t_Ww,     262144,  30, FM, 0};
        RA.e[3]  = {R_w,        t_Rw,     262144,  30, FM, 0};
        RA.e[4]  = {P_w,        t_Pw,     65536,   30, FM, 0};
        RA.e[5]  = {V_w,        t_Vw,     131072,  30, FM, 0};
        RA.e[6]  = {U_w,        t_Uw,     65536,   30, FM, 0};
        RA.e[7]  = {D_w,        t_Dw,     65536,   30, FM, 0};
        RA.e[8]  = {ff_w1,      t_ff1,    1048576, 30, FM, 0};
        RA.e[9]  = {ff_w2,      t_ff2,    1048576, 30, FM, 0};
        RA.e[10] = {hidden_prev, hpt,     SB * EMB, 30, FM, 0};
        RA.e[11] = {stack_prev,  stt,     SB * SWIDTH, 7, 127, SDEPTH * SWIDTH};
        round_multi<<<2048, 256>>>(RA);
    }

    // 1. LN1 (tf32-rounded output)
    ln_kernel<<<SB, 128>>>(x_in, ln1_g, ln1_b, h1);

    // 2. QKV projection
    {
        GemmArgs P{};
        P.A0 = h1; P.W0 = t_inproj; P.b0 = in_proj_b; P.C = qkvb;
        P.M = SB; P.N = 3 * EMB; P.K = EMB;
        launch_gemm<0>(P);
    }

    // 3. Attention (causal flash, tf32-rounded output)
    attn_kernel<<<dim3(SEQ / 64, BATCH * NHEADS), 256, ATTN_SMEM>>>(qkvb, k_mask, attb);

    // 4. Output projection + residual -> x (full) + xt (rounded)
    {
        GemmArgs P{};
        P.A0 = attb; P.W0 = t_outprj; P.b0 = out_proj_b; P.res = x_in;
        P.C = xb; P.C2 = xt;
        P.M = SB; P.N = EMB; P.K = EMB;
        launch_gemm<2>(P);
    }

    // 5. hidden = nonsat(xt@W^T + hpt@R^T + stt@P^T + biases) -> out_hidden + ht
    {
        GemmArgs P{};
        P.A0 = xt; P.A1 = hpt; P.A2 = stt;
        P.W0 = t_Ww; P.W1 = t_Rw; P.W2 = t_Pw;
        P.b0 = W_b; P.b1 = R_b; P.b2 = P_b;
        P.C = out_hidden; P.C2 = ht;
        P.M = SB; P.N = EMB; P.K = 1152;
        launch_gemm<3>(P);
    }

    // 6. logits = [xt | ht^T] @ V_w^T
    {
        GemmArgs P{};
        P.A0 = xt; P.A1 = ht; P.W0 = t_Vw; P.C = lg;
        P.M = SB; P.N = DSS; P.K = 1024;
        launch_gemm<4>(P);
    }

    // 7. softmax over 128 (tf32-rounded)
    softmax128_kernel<<<SB, 128>>>(lg);

    // 8. x = 0.5*(x + p @ U_w^T)
    {
        GemmArgs P{};
        P.A0 = lg; P.W0 = t_Uw; P.res = xb; P.C = xb;
        P.M = SB; P.N = EMB; P.K = DSS;
        launch_gemm<5>(P);
    }

    // 9. stack_inp = nonsat(ht @ D_w^T + D_b)
    {
        GemmArgs P{};
        P.A0 = ht; P.W0 = t_Dw; P.b0 = D_b; P.C = si;
        P.M = SB; P.N = SWIDTH; P.K = EMB;
        launch_gemm<6>(P);
    }

    // 10. controls
    controls_kernel<<<SB, 128>>>(out_hidden, A_w, A_b, ctl);

    // 11. stack update
    stack_kernel<<<SB, 128>>>(stack_prev, si, ctl, out_stack);

    // 12. LN2 (tf32-rounded output)
    ln_kernel<<<SB, 128>>>(xb, ln2_g, ln2_b, h2);

    // 13. FF1 (relu, tf32-rounded output)
    {
        GemmArgs P{};
        P.A0 = h2; P.W0 = t_ff1; P.b0 = ff_b1; P.C = f1;
        P.M = SB; P.N = DFF; P.K = EMB;
        launch_gemm<1>(P);
    }

    // 14. FF2 + residual -> out_x
    {
        GemmArgs P{};
        P.A0 = f1; P.W0 = t_ff2; P.b0 = ff_b2; P.res = xb; P.C = out_x;
        P.M = SB; P.N = EMB; P.K = DFF;
        launch_gemm<2>(P);
    }
}

// round 11
// speedup vs baseline: 1.7110x; 1.0925x over previous
#include <cuda_runtime.h>
#include <cuda_bf16.h>
#include <cstdint>

// Problem dims
#define SEQ 512
#define BATCH 16
#define EMB 512
#define SB 8192           // SEQ*BATCH rows
#define DFF 2048
#define DSS 128
#define SDEPTH 48
#define SWIDTH 128
#define NHEADS 8
#define HDIM 64

// ---------------- scratch (device globals; no allocation) ----------------
__device__ float g_h1 [SB * EMB];
__device__ float g_qkv[SB * 3 * EMB];
__device__ float g_att[SB * EMB];
__device__ float g_x  [SB * EMB];
__device__ float g_xt [SB * EMB];      // tf32-rounded copy of x
__device__ float g_ht [SB * EMB];      // tf32-rounded copy of hidden
__device__ float g_hpt[SB * EMB];      // tf32-rounded hidden_prev
__device__ float g_stt[SB * SWIDTH];   // tf32-rounded stack top slice
__device__ float g_lg [SB * DSS];
__device__ float g_si [SB * SWIDTH];
__device__ float g_ctl[SB * 3];
__device__ float g_h2 [SB * EMB];
__device__ float g_f1 [SB * DFF];
__device__ float g_wt [3997696];       // tf32-rounded weights pool

// ---------------- helpers ----------------
__device__ __forceinline__ float nonsat_f(float x) {
    // Newton for y^3/3 + y = x ; reference's step() IS the Newton update.
    float y = x;
#pragma unroll
    for (int i = 0; i < 20; i++) {
        float y2 = y * y;
        y = __fdividef(0.6666666666666666f * y2 * y + x, y2 + 1.0f);
    }
    return y;
}

__device__ __forceinline__ uint32_t to_tf32(float x) {
    uint32_t r;
    asm("cvt.rna.tf32.f32 %0, %1;" : "=r"(r) : "f"(x));
    return r;
}
__device__ __forceinline__ float rtf(float x) { return __uint_as_float(to_tf32(x)); }

__device__ __forceinline__ void mma_tf32(float (&c)[4], const uint32_t (&a)[4], const uint32_t (&b)[2]) {
    asm volatile(
        "mma.sync.aligned.m16n8k8.row.col.f32.tf32.tf32.f32 "
        "{%0,%1,%2,%3},{%4,%5,%6,%7},{%8,%9},{%0,%1,%2,%3};"
        : "+f"(c[0]), "+f"(c[1]), "+f"(c[2]), "+f"(c[3])
        : "r"(a[0]), "r"(a[1]), "r"(a[2]), "r"(a[3]), "r"(b[0]), "r"(b[1]));
}

__device__ __forceinline__ void cp16(uint32_t dst, const float* src) {
    asm volatile("cp.async.cg.shared.global [%0], [%1], 16;" :: "r"(dst), "l"(src));
}
#define CP_COMMIT() asm volatile("cp.async.commit_group;")
#define CP_WAIT1()  asm volatile("cp.async.wait_group 1;")

// ---------------- pre-round pass: tf32-round tensors into scratch ----------------
struct RoundEntry { const float* src; float* dst; int n; int shift; int mask; int stride; };
struct RoundArgs { RoundEntry e[12]; };

__global__ void __launch_bounds__(256) round_multi(RoundArgs A) {
    const int gs = gridDim.x * blockDim.x;
    const int t0 = blockIdx.x * blockDim.x + threadIdx.x;
#pragma unroll 1
    for (int i = 0; i < 12; i++) {
        const RoundEntry E = A.e[i];
        for (int idx = t0; idx < E.n; idx += gs) {
            int row = idx >> E.shift;
            int col = idx & E.mask;
            E.dst[idx] = rtf(E.src[(size_t)row * E.stride + col]);
        }
    }
}

// ---------------- GEMM: C[M,N] = A[M,K] @ W[N,K]^T + epilogue ----------------
struct GemmArgs {
    const float* A0; const float* A1; const float* A2;
    const float* W0; const float* W1; const float* W2;
    const float* b0; const float* b1; const float* b2;
    const float* res;
    float* C;
    float* C2;     // optional tf32-rounded twin output
    int M, N, K;
};

// MODE: 0=+bias  1=+bias,relu,round  2=+bias+res(+C2 round)  3=hidden(3src,+3bias,nonsat,+C2)
//       4=logits(2src,nobias)  5=mix(res: 0.5*(res+acc))  6=+bias,nonsat
template<int MODE>
__device__ __forceinline__ const float* addrA(const GemmArgs& P, int grow, int gk) {
    if constexpr (MODE == 3) {
        if (gk < 512) {
            int xr = ((grow & 511) << 4) + (grow >> 9);
            return &P.A0[(size_t)xr * 512 + gk];
        } else if (gk < 1024) {
            return &P.A1[(size_t)grow * 512 + (gk - 512)];
        } else {
            return &P.A2[(size_t)grow * 128 + (gk - 1024)];
        }
    } else if constexpr (MODE == 4) {
        if (gk < 512) return &P.A0[(size_t)grow * 512 + gk];
        int hr = ((grow & 15) << 9) + (grow >> 4);
        return &P.A1[(size_t)hr * 512 + (gk - 512)];
    } else {
        return &P.A0[(size_t)grow * (size_t)P.K + gk];
    }
}

template<int MODE>
__device__ __forceinline__ const float* addrW(const GemmArgs& P, int n, int gk) {
    if constexpr (MODE == 3) {
        if (gk < 512)       return &P.W0[(size_t)n * 512 + gk];
        else if (gk < 1024) return &P.W1[(size_t)n * 512 + (gk - 512)];
        else                return &P.W2[(size_t)n * 128 + (gk - 1024)];
    } else {
        return &P.W0[(size_t)n * (size_t)P.K + gk];
    }
}

// 128x128x16 tile, 256 threads = 8 warps (2x4), 3-stage cp.async ring.
template<int MODE>
__global__ void __launch_bounds__(256) gemm_tc(GemmArgs P) {
    __shared__ uint32_t As[3][2048];
    __shared__ uint32_t Bs[3][2048];

    const int tid  = threadIdx.x;
    const int lane = tid & 31;
    const int warp = tid >> 5;
    const int wm = warp >> 2;
    const int wn = warp & 3;
    const int bn = blockIdx.x, bm = blockIdx.y;
    const int row0 = bm * 128, col0 = bn * 128;

    const int r0 = tid >> 2;
    const int c4 = tid & 3;

    const int g  = lane >> 2;
    const int kq = lane & 3;
    const int swz = (g >> 1) & 3;

    const int nst = P.K >> 4;

    int offs[2];
    uint32_t rA[2], rB[2];
#pragma unroll
    for (int li = 0; li < 2; li++) {
        int r = r0 + li * 64;
        offs[li] = r * 16 + ((c4 ^ ((r >> 1) & 3)) << 2);
        rA[li] = row0 + r;
        rB[li] = col0 + r;
    }

    auto issue = [&](int s, int b) {
        int kt = (s << 4) + c4 * 4;
#pragma unroll
        for (int li = 0; li < 2; li++) {
            cp16((uint32_t)__cvta_generic_to_shared(&As[b][offs[li]]), addrA<MODE>(P, rA[li], kt));
            cp16((uint32_t)__cvta_generic_to_shared(&Bs[b][offs[li]]), addrW<MODE>(P, rB[li], kt));
        }
    };

    issue(0, 0);
    CP_COMMIT();
    if (nst > 1) issue(1, 1);
    CP_COMMIT();

    float acc[4][4][4];
#pragma unroll
    for (int i = 0; i < 4; i++)
#pragma unroll
        for (int j = 0; j < 4; j++)
#pragma unroll
            for (int e = 0; e < 4; e++) acc[i][j][e] = 0.f;

    int buf = 0, pbuf = 2;
#pragma unroll 1
    for (int s = 0; s < nst; s++) {
        CP_WAIT1();
        __syncthreads();
        if (s + 2 < nst) issue(s + 2, pbuf);
        CP_COMMIT();

#pragma unroll
        for (int ks = 0; ks < 2; ks++) {
            const int grp0 = ((2 * ks) ^ swz) << 2;
            const int grp1 = grp0 ^ 4;
            uint32_t af[4][4];
            uint32_t bf[4][2];
#pragma unroll
            for (int tmi = 0; tmi < 4; tmi++) {
                const uint32_t* A_ = &As[buf][(wm * 64 + tmi * 16 + g) * 16 + kq];
                af[tmi][0] = A_[grp0];
                af[tmi][1] = A_[128 + grp0];
                af[tmi][2] = A_[grp1];
                af[tmi][3] = A_[128 + grp1];
            }
#pragma unroll
            for (int tni = 0; tni < 4; tni++) {
                const uint32_t* B_ = &Bs[buf][(wn * 32 + tni * 8 + g) * 16 + kq];
                bf[tni][0] = B_[grp0];
                bf[tni][1] = B_[grp1];
            }
#pragma unroll
            for (int tmi = 0; tmi < 4; tmi++)
#pragma unroll
                for (int tni = 0; tni < 4; tni++)
                    mma_tf32(acc[tmi][tni], af[tmi], bf[tni]);
        }
        buf  = (buf == 2)  ? 0 : buf + 1;
        pbuf = (pbuf == 2) ? 0 : pbuf + 1;
    }

    const int q = lane & 3;
#pragma unroll
    for (int tmi = 0; tmi < 4; tmi++) {
        int rb = row0 + wm * 64 + tmi * 16;
#pragma unroll
        for (int h2 = 0; h2 < 2; h2++) {
            int gm = rb + g + h2 * 8;
#pragma unroll
            for (int tni = 0; tni < 4; tni++) {
                int gn = col0 + wn * 32 + tni * 8 + q * 2;
                float v0 = acc[tmi][tni][h2 * 2 + 0];
                float v1 = acc[tmi][tni][h2 * 2 + 1];
                if constexpr (MODE == 0) { v0 += P.b0[gn]; v1 += P.b0[gn + 1]; }
                else if constexpr (MODE == 1) {
                    v0 = rtf(fmaxf(v0 + P.b0[gn], 0.f));
                    v1 = rtf(fmaxf(v1 + P.b0[gn + 1], 0.f));
                } else if constexpr (MODE == 2) {
                    const float* rp = &P.res[(size_t)gm * P.N + gn];
                    v0 = v0 + P.b0[gn] + rp[0];
                    v1 = v1 + P.b0[gn + 1] + rp[1];
                } else if constexpr (MODE == 3) {
                    v0 = nonsat_f(v0 + P.b0[gn] + P.b1[gn] + P.b2[gn]);
                    v1 = nonsat_f(v1 + P.b0[gn + 1] + P.b1[gn + 1] + P.b2[gn + 1]);
                } else if constexpr (MODE == 4) {
                    /* raw */
                } else if constexpr (MODE == 5) {
                    const float* rp = &P.res[(size_t)gm * P.N + gn];
                    v0 = 0.5f * (rp[0] + v0);
                    v1 = 0.5f * (rp[1] + v1);
                } else if constexpr (MODE == 6) {
                    v0 = nonsat_f(v0 + P.b0[gn]);
                    v1 = nonsat_f(v1 + P.b0[gn + 1]);
                }
                *(float2*)&P.C[(size_t)gm * P.N + gn] = make_float2(v0, v1);
                if constexpr (MODE == 2 || MODE == 3) {
                    if (P.C2)
                        *(float2*)&P.C2[(size_t)gm * P.N + gn] = make_float2(rtf(v0), rtf(v1));
                }
            }
        }
    }
}

// ---------------- LayerNorm (row of 512), output tf32-rounded ----------------
__global__ void __launch_bounds__(128) ln_kernel(const float* __restrict__ x,
                                                 const float* __restrict__ g,
                                                 const float* __restrict__ b,
                                                 float* __restrict__ out) {
    const int r = blockIdx.x, t = threadIdx.x;
    const float* row = x + (size_t)r * 512;
    float v0 = row[t], v1 = row[t + 128], v2 = row[t + 256], v3 = row[t + 384];
    __shared__ float sh[4];
    float s = v0 + v1 + v2 + v3;
#pragma unroll
    for (int o = 16; o; o >>= 1) s += __shfl_xor_sync(0xffffffffu, s, o);
    if ((t & 31) == 0) sh[t >> 5] = s;
    __syncthreads();
    float mean = (sh[0] + sh[1] + sh[2] + sh[3]) * (1.f / 512.f);
    __syncthreads();
    float d0 = v0 - mean, d1 = v1 - mean, d2 = v2 - mean, d3 = v3 - mean;
    float q = d0 * d0 + d1 * d1 + d2 * d2 + d3 * d3;
#pragma unroll
    for (int o = 16; o; o >>= 1) q += __shfl_xor_sync(0xffffffffu, q, o);
    if ((t & 31) == 0) sh[t >> 5] = q;
    __syncthreads();
    float var = (sh[0] + sh[1] + sh[2] + sh[3]) * (1.f / 512.f);
    float rstd = rsqrtf(var + 1e-5f);
    float* orow = out + (size_t)r * 512;
    orow[t]       = rtf(d0 * rstd * g[t]       + b[t]);
    orow[t + 128] = rtf(d1 * rstd * g[t + 128] + b[t + 128]);
    orow[t + 256] = rtf(d2 * rstd * g[t + 256] + b[t + 256]);
    orow[t + 384] = rtf(d3 * rstd * g[t + 384] + b[t + 384]);
}

// ---------------- Flash attention, tf32 tensor-core (64x64 tiles, causal) ------
// Per block: one (qt, b, h). 256 threads = 8 warps (wm 0..1 x wn 0..3).
// MMA1: S = Q@K^T (m16n8k8 tf32), fragments -> Pt[c][r] (pitch 68).
// softmax on Pt (online, rowwise), probs written tf32-rounded into Ps (A-layout).
// MMA2: O += Ps @ Vt^T, accumulators rescaled by online correction.
#define AP 72   // pitch for swizzled A/B-layout tiles
__global__ void __launch_bounds__(256) attn_kernel(const float* __restrict__ qkv,
                                                   const unsigned char* __restrict__ kmask,
                                                   float* __restrict__ out) {
    extern __shared__ float sm[];
    float* Qs   = sm;                 // [64][AP]
    float* Ks   = Qs + 64 * AP;       // [64][AP]
    float* Vt   = Ks + 64 * AP;       // [64 d][AP] (transposed V)
    float* Ps   = Vt + 64 * AP;       // [64 q][AP] probs
    float* Pt   = Ps + 64 * AP;       // [64 c][68] scores (transposed)
    float* mrow = Pt + 64 * 68;       // 64
    float* lrow = mrow + 64;          // 64
    float* rsc  = lrow + 64;          // 64
    float* kmf  = rsc + 64;           // 64

    const int tid = threadIdx.x;
    const int qt = blockIdx.x;        // 0..7
    const int bh = blockIdx.y;        // 0..127
    const int b = bh >> 3, h = bh & 7;
    const int lane = tid & 31;
    const int warp = tid >> 5;
    const int wm = warp >> 1;         // unused split; use 2x4 below
    const int wrow = warp >> 2;       // 0..1 -> 32-row half
    const int wcol = warp & 3;        // 0..3 -> 16-col quarter
    const int g  = lane >> 2;         // 0..7
    const int kq = lane & 3;          // 0..3
    (void)wm;

    // ---- load Q tile (rows r, cols d), prescaled + rounded ----
#pragma unroll
    for (int li = 0; li < 4; li++) {
        int idx = tid + li * 256;
        int g4 = idx & 15, r = idx >> 4;
        const float4 q = *(const float4*)&qkv[(size_t)((qt * 64 + r) * 16 + b) * 1536 + h * 64 + g4 * 4];
        float* d = &Qs[r * AP + ((g4 ^ (r & 7)) << 2)];
        d[0] = rtf(q.x * 0.125f);
        d[1] = rtf(q.y * 0.125f);
        d[2] = rtf(q.z * 0.125f);
        d[3] = rtf(q.w * 0.125f);
    }
    if (tid < 64) { mrow[tid] = -1e30f; lrow[tid] = 0.f; }

    float Oa[2][2][4];
#pragma unroll
    for (int i = 0; i < 2; i++)
#pragma unroll
        for (int j = 0; j < 2; j++)
#pragma unroll
            for (int e = 0; e < 4; e++) Oa[i][j][e] = 0.f;
    __syncthreads();

    const int rb0 = wrow * 32;        // warp row base (q rows / also d rows for MMA2 cols? no)
    const int cb0 = wcol * 16;        // warp col base (keys for MMA1, d for MMA2)

    for (int kt = 0; kt <= qt; kt++) {
        // ---- load K tile [c][d] and V transposed [d][c] ----
#pragma unroll
        for (int li = 0; li < 4; li++) {
            int idx = tid + li * 256;
            int g4 = idx & 15, c = idx >> 4;
            size_t base = (size_t)((kt * 64 + c) * 16 + b) * 1536 + h * 64;
            const float4 kv = *(const float4*)&qkv[base + 512 + g4 * 4];
            float* d = &Ks[c * AP + ((g4 ^ (c & 7)) << 2)];
            d[0] = rtf(kv.x); d[1] = rtf(kv.y); d[2] = rtf(kv.z); d[3] = rtf(kv.w);
        }
#pragma unroll
        for (int li = 0; li < 4; li++) {
            int idx = tid + li * 256;
            int c = idx & 63, d4 = idx >> 6;
            size_t base = (size_t)((kt * 64 + c) * 16 + b) * 1536 + h * 64 + 1024;
            const float4 vv = *(const float4*)&qkv[base + d4 * 4];
            float v[4] = {vv.x, vv.y, vv.z, vv.w};
#pragma unroll
            for (int j = 0; j < 4; j++) {
                int dd = d4 * 4 + j;
                Vt[dd * AP + (((c >> 2) ^ (dd & 7)) << 2) + (c & 3)] = rtf(v[j]);
            }
        }
        if (tid < 64) kmf[tid] = kmask[b * 512 + kt * 64 + tid] ? -1e30f : 0.f;
        __syncthreads();

        // ---- MMA1: S = Q @ K^T ----
        float sc[2][2][4];
#pragma unroll
        for (int i = 0; i < 2; i++)
#pragma unroll
            for (int j = 0; j < 2; j++)
#pragma unroll
                for (int e = 0; e < 4; e++) sc[i][j][e] = 0.f;
#pragma unroll
        for (int ks = 0; ks < 8; ks++) {
            const int G0 = ((2 * ks) ^ g) << 2;
            const int G1 = ((2 * ks + 1) ^ g) << 2;
            uint32_t af[2][4], bf[2][2];
#pragma unroll
            for (int tm = 0; tm < 2; tm++) {
                const uint32_t* A_ = (const uint32_t*)&Qs[(rb0 + tm * 16 + g) * AP + kq];
                af[tm][0] = A_[G0];
                af[tm][1] = A_[8 * AP + G0];
                af[tm][2] = A_[G1];
                af[tm][3] = A_[8 * AP + G1];
            }
#pragma unroll
            for (int tn = 0; tn < 2; tn++) {
                const uint32_t* B_ = (const uint32_t*)&Ks[(cb0 + tn * 8 + g) * AP + kq];
                bf[tn][0] = B_[G0];
                bf[tn][1] = B_[G1];
            }
#pragma unroll
            for (int tm = 0; tm < 2; tm++)
#pragma unroll
                for (int tn = 0; tn < 2; tn++)
                    mma_tf32(sc[tm][tn], af[tm], bf[tn]);
        }

        // ---- mask + store scores to Pt[c][r] ----
        const bool diag = (kt == qt);
#pragma unroll
        for (int tm = 0; tm < 2; tm++) {
#pragma unroll
            for (int tn = 0; tn < 2; tn++) {
#pragma unroll
                for (int e = 0; e < 4; e++) {
                    int r = rb0 + tm * 16 + g + (e >> 1) * 8;
                    int c = cb0 + tn * 8 + 2 * kq + (e & 1);
                    float val = sc[tm][tn][e] + kmf[c];
                    if (diag && c > r) val = -1e30f;
                    Pt[c * 68 + r] = val;
                }
            }
        }
        __syncthreads();

        // ---- online softmax on Pt; probs -> Ps (rounded) ----
        {
            int r = tid >> 2, q4 = tid & 3;
            float mx = -1e30f;
#pragma unroll
            for (int cc = 0; cc < 16; cc++) mx = fmaxf(mx, Pt[(q4 * 16 + cc) * 68 + r]);
            mx = fmaxf(mx, __shfl_xor_sync(0xffffffffu, mx, 1));
            mx = fmaxf(mx, __shfl_xor_sync(0xffffffffu, mx, 2));
            float mold = mrow[r];
            float mnew = fmaxf(mold, mx);
            float sum = 0.f;
#pragma unroll
            for (int cc = 0; cc < 16; cc++) {
                int c = q4 * 16 + cc;
                float p = __expf(Pt[c * 68 + r] - mnew);
                Ps[r * AP + (((c >> 2) ^ (r & 7)) << 2) + (c & 3)] = rtf(p);
                sum += p;
            }
            sum += __shfl_xor_sync(0xffffffffu, sum, 1);
            sum += __shfl_xor_sync(0xffffffffu, sum, 2);
            if (q4 == 0) {
                float scale = __expf(mold - mnew);
                mrow[r] = mnew;
                lrow[r] = lrow[r] * scale + sum;
                rsc[r] = scale;
            }
        }
        __syncthreads();

        // ---- rescale accumulators, then MMA2: O += P @ V ----
#pragma unroll
        for (int tm = 0; tm < 2; tm++) {
            float s0 = rsc[rb0 + tm * 16 + g];
            float s1 = rsc[rb0 + tm * 16 + g + 8];
#pragma unroll
            for (int tn = 0; tn < 2; tn++) {
                Oa[tm][tn][0] *= s0; Oa[tm][tn][1] *= s0;
                Oa[tm][tn][2] *= s1; Oa[tm][tn][3] *= s1;
            }
        }
#pragma unroll
        for (int ks = 0; ks < 8; ks++) {
            const int G0 = ((2 * ks) ^ g) << 2;
            const int G1 = ((2 * ks + 1) ^ g) << 2;
            uint32_t af[2][4], bf[2][2];
#pragma unroll
            for (int tm = 0; tm < 2; tm++) {
                const uint32_t* A_ = (const uint32_t*)&Ps[(rb0 + tm * 16 + g) * AP + kq];
                af[tm][0] = A_[G0];
                af[tm][1] = A_[8 * AP + G0];
                af[tm][2] = A_[G1];
                af[tm][3] = A_[8 * AP + G1];
            }
#pragma unroll
            for (int tn = 0; tn < 2; tn++) {
                const uint32_t* B_ = (const uint32_t*)&Vt[(cb0 + tn * 8 + g) * AP + kq];
                bf[tn][0] = B_[G0];
                bf[tn][1] = B_[G1];
            }
#pragma unroll
            for (int tm = 0; tm < 2; tm++)
#pragma unroll
                for (int tn = 0; tn < 2; tn++)
                    mma_tf32(Oa[tm][tn], af[tm], bf[tn]);
        }
        __syncthreads();
    }

    // ---- finalize: O / lrow, rounded, to gmem ----
#pragma unroll
    for (int tm = 0; tm < 2; tm++) {
#pragma unroll
        for (int e2 = 0; e2 < 2; e2++) {
            int r = rb0 + tm * 16 + g + e2 * 8;
            float inv = __fdividef(1.f, lrow[r]);
#pragma unroll
            for (int tn = 0; tn < 2; tn++) {
                int d = cb0 + tn * 8 + 2 * kq;
                float v0 = rtf(Oa[tm][tn][e2 * 2 + 0] * inv);
                float v1 = rtf(Oa[tm][tn][e2 * 2 + 1] * inv);
                *(float2*)&out[(size_t)((qt * 64 + r) * 16 + b) * 512 + h * 64 + d] =
                    make_float2(v0, v1);
            }
        }
    }
}

// ---------------- softmax over 128 (mixture logits), output tf32-rounded -------
__global__ void __launch_bounds__(128) softmax128_kernel(float* __restrict__ lg) {
    const int r = blockIdx.x, t = threadIdx.x;
    float v = lg[(size_t)r * 128 + t];
    __shared__ float sh[4];
    float m = v;
#pragma unroll
    for (int o = 16; o; o >>= 1) m = fmaxf(m, __shfl_xor_sync(0xffffffffu, m, o));
    if ((t & 31) == 0) sh[t >> 5] = m;
    __syncthreads();
    m = fmaxf(fmaxf(sh[0], sh[1]), fmaxf(sh[2], sh[3]));
    float e = __expf(v - m);
    __syncthreads();
    float s = e;
#pragma unroll
    for (int o = 16; o; o >>= 1) s += __shfl_xor_sync(0xffffffffu, s, o);
    if ((t & 31) == 0) sh[t >> 5] = s;
    __syncthreads();
    s = sh[0] + sh[1] + sh[2] + sh[3];
    lg[(size_t)r * 128 + t] = rtf(e * __fdividef(1.f, s));
}

// ---------------- stack controls: softmax(hidden @ A_w^T + A_b) ----------------
__global__ void __launch_bounds__(128) controls_kernel(const float* __restrict__ hidden,
                                                       const float* __restrict__ Aw,
                                                       const float* __restrict__ Ab,
                                                       float* __restrict__ ctl) {
    const int r = blockIdx.x, t = threadIdx.x;
    const float* row = hidden + (size_t)r * 512;
    float s0 = 0.f, s1 = 0.f, s2 = 0.f;
#pragma unroll
    for (int i = 0; i < 4; i++) {
        int c = t + i * 128;
        float hv = row[c];
        s0 += hv * Aw[c];
        s1 += hv * Aw[512 + c];
        s2 += hv * Aw[1024 + c];
    }
    __shared__ float sh[3][4];
#pragma unroll
    for (int o = 16; o; o >>= 1) {
        s0 += __shfl_xor_sync(0xffffffffu, s0, o);
        s1 += __shfl_xor_sync(0xffffffffu, s1, o);
        s2 += __shfl_xor_sync(0xffffffffu, s2, o);
    }
    if ((t & 31) == 0) { sh[0][t >> 5] = s0; sh[1][t >> 5] = s1; sh[2][t >> 5] = s2; }
    __syncthreads();
    if (t == 0) {
        float c0 = sh[0][0] + sh[0][1] + sh[0][2] + sh[0][3] + Ab[0];
        float c1 = sh[1][0] + sh[1][1] + sh[1][2] + sh[1][3] + Ab[1];
        float c2 = sh[2][0] + sh[2][1] + sh[2][2] + sh[2][3] + Ab[2];
        float m = fmaxf(c0, fmaxf(c1, c2));
        float e0 = __expf(c0 - m), e1 = __expf(c1 - m), e2 = __expf(c2 - m);
        float inv = __fdividef(1.f, e0 + e1 + e2);
        ctl[r * 3 + 0] = e0 * inv;
        ctl[r * 3 + 1] = e1 * inv;
        ctl[r * 3 + 2] = e2 * inv;
    }
}

// ---------------- stack update ----------------
__global__ void __launch_bounds__(128) stack_kernel(const float* __restrict__ stack_prev,
                                                    const float* __restrict__ si,
                                                    const float* __restrict__ ctl,
                                                    float* __restrict__ out) {
    const int g = blockIdx.x;
    const int w = threadIdx.x;
    const float* prev = stack_prev + (size_t)g * (SDEPTH * SWIDTH);
    float* o = out + (size_t)g * (SDEPTH * SWIDTH);
    const float cpush = ctl[g * 3 + 0];
    const float cpop  = ctl[g * 3 + 1];
    const float cnoop = ctl[g * 3 + 2];
    float pm1 = si[(size_t)g * 128 + w];
    float p0 = prev[w];
#pragma unroll 4
    for (int d = 0; d < SDEPTH; d++) {
        float p1 = (d < SDEPTH - 1) ? prev[(d + 1) * SWIDTH + w] : 0.f;
        o[d * SWIDTH + w] = cnoop * p0 + cpush * pm1 + cpop * p1;
        pm1 = p0;
        p0 = p1;
    }
}

// ---------------- host ----------------
template<int MODE>
static void launch_gemm(const GemmArgs& P) {
    dim3 grid(P.N / 128, P.M / 128);
    gemm_tc<MODE><<<grid, 256>>>(P);
}

extern "C" void kernel_launch(void* const* d_in, const int* in_sizes, int n_in,
                              void* d_out, int out_size) {
    const float* x_in        = (const float*)d_in[0];
    const float* hidden_prev = (const float*)d_in[1];
    const float* stack_prev  = (const float*)d_in[2];
    const unsigned char* k_mask = (const unsigned char*)d_in[3];
    const float* in_proj_w  = (const float*)d_in[4];
    const float* in_proj_b  = (const float*)d_in[5];
    const float* out_proj_w = (const float*)d_in[6];
    const float* out_proj_b = (const float*)d_in[7];
    const float* ln1_g = (const float*)d_in[8];
    const float* ln1_b = (const float*)d_in[9];
    const float* ln2_g = (const float*)d_in[10];
    const float* ln2_b = (const float*)d_in[11];
    const float* ff_w1 = (const float*)d_in[12];
    const float* ff_b1 = (const float*)d_in[13];
    const float* ff_w2 = (const float*)d_in[14];
    const float* ff_b2 = (const float*)d_in[15];
    const float* W_w = (const float*)d_in[16];
    const float* W_b = (const float*)d_in[17];
    const float* R_w = (const float*)d_in[18];
    const float* R_b = (const float*)d_in[19];
    const float* P_w = (const float*)d_in[20];
    const float* P_b = (const float*)d_in[21];
    const float* V_w = (const float*)d_in[22];
    const float* U_w = (const float*)d_in[23];
    const float* A_w = (const float*)d_in[24];
    const float* A_b = (const float*)d_in[25];
    const float* D_w = (const float*)d_in[26];
    const float* D_b = (const float*)d_in[27];

    float *h1, *qkvb, *attb, *xb, *xt, *ht, *hpt, *stt, *lg, *si, *ctl, *h2, *f1, *wt;
    cudaGetSymbolAddress((void**)&h1,  g_h1);
    cudaGetSymbolAddress((void**)&qkvb, g_qkv);
    cudaGetSymbolAddress((void**)&attb, g_att);
    cudaGetSymbolAddress((void**)&xb,  g_x);
    cudaGetSymbolAddress((void**)&xt,  g_xt);
    cudaGetSymbolAddress((void**)&ht,  g_ht);
    cudaGetSymbolAddress((void**)&hpt, g_hpt);
    cudaGetSymbolAddress((void**)&stt, g_stt);
    cudaGetSymbolAddress((void**)&lg,  g_lg);
    cudaGetSymbolAddress((void**)&si,  g_si);
    cudaGetSymbolAddress((void**)&ctl, g_ctl);
    cudaGetSymbolAddress((void**)&h2,  g_h2);
    cudaGetSymbolAddress((void**)&f1,  g_f1);
    cudaGetSymbolAddress((void**)&wt,  g_wt);

    float* t_inproj = wt + 0;
    float* t_outprj = wt + 786432;
    float* t_Ww     = wt + 1048576;
    float* t_Rw     = wt + 1310720;
    float* t_Pw     = wt + 1572864;
    float* t_Vw     = wt + 1638400;
    float* t_Uw     = wt + 1769472;
    float* t_Dw     = wt + 1835008;
    float* t_ff1    = wt + 1900544;
    float* t_ff2    = wt + 2949120;

    float* out_x      = (float*)d_out;
    float* out_hidden = out_x + (size_t)SB * EMB;
    float* out_stack  = out_hidden + (size_t)SB * EMB;

    const int ATTN_SMEM = (4 * 64 * AP + 64 * 68 + 4 * 64) * (int)sizeof(float);
    cudaFuncSetAttribute(attn_kernel, cudaFuncAttributeMaxDynamicSharedMemorySize, ATTN_SMEM);

    // 0. pre-round weights + hidden_prev + stack top to tf32-exact fp32
    {
        const int FM = 0x3FFFFFFF;
        RoundArgs RA{};
        RA.e[0]  = {in_proj_w,  t_inproj, 786432,  30, FM, 0};
        RA.e[1]  = {out_proj_w, t_outprj, 262144,  30, FM, 0};
        RA.e[2]  = {W_w,        t_Ww,     262144,  30, FM, 0};
        RA.e[3]  = {R_w,        t_Rw,     262144,  30, FM, 0};
        RA.e[4]  = {P_w,        t_Pw,     65536,   30, FM, 0};
        RA.e[5]  = {V_w,        t_Vw,     131072,  30, FM, 0};
        RA.e[6]  = {U_w,        t_Uw,     65536,   30, FM, 0};
        RA.e[7]  = {D_w,        t_Dw,     65536,   30, FM, 0};
        RA.e[8]  = {ff_w1,      t_ff1,    1048576, 30, FM, 0};
        RA.e[9]  = {ff_w2,      t_ff2,    1048576, 30, FM, 0};
        RA.e[10] = {hidden_prev, hpt,     SB * EMB, 30, FM, 0};
        RA.e[11] = {stack_prev,  stt,     SB * SWIDTH, 7, 127, SDEPTH * SWIDTH};
        round_multi<<<2048, 256>>>(RA);
    }

    // 1. LN1 (tf32-rounded output)
    ln_kernel<<<SB, 128>>>(x_in, ln1_g, ln1_b, h1);

    // 2. QKV projection
    {
        GemmArgs P{};
        P.A0 = h1; P.W0 = t_inproj; P.b0 = in_proj_b; P.C = qkvb;
        P.M = SB; P.N = 3 * EMB; P.K = EMB;
        launch_gemm<0>(P);
    }

    // 3. Attention (causal flash, tf32 tensor cores)
    attn_kernel<<<dim3(SEQ / 64, BATCH * NHEADS), 256, ATTN_SMEM>>>(qkvb, k_mask, attb);

    // 4. Output projection + residual -> x (full) + xt (rounded)
    {
        GemmArgs P{};
        P.A0 = attb; P.W0 = t_outprj; P.b0 = out_proj_b; P.res = x_in;
        P.C = xb; P.C2 = xt;
        P.M = SB; P.N = EMB; P.K = EMB;
        launch_gemm<2>(P);
    }

    // 5. hidden = nonsat(xt@W^T + hpt@R^T + stt@P^T + biases) -> out_hidden + ht
    {
        GemmArgs P{};
        P.A0 = xt; P.A1 = hpt; P.A2 = stt;
        P.W0 = t_Ww; P.W1 = t_Rw; P.W2 = t_Pw;
        P.b0 = W_b; P.b1 = R_b; P.b2 = P_b;
        P.C = out_hidden; P.C2 = ht;
        P.M = SB; P.N = EMB; P.K = 1152;
        launch_gemm<3>(P);
    }

    // 6. logits = [xt | ht^T] @ V_w^T
    {
        GemmArgs P{};
        P.A0 = xt; P.A1 = ht; P.W0 = t_Vw; P.C = lg;
        P.M = SB; P.N = DSS; P.K = 1024;
        launch_gemm<4>(P);
    }

    // 7. softmax over 128 (tf32-rounded)
    softmax128_kernel<<<SB, 128>>>(lg);

    // 8. x = 0.5*(x + p @ U_w^T)
    {
        GemmArgs P{};
        P.A0 = lg; P.W0 = t_Uw; P.res = xb; P.C = xb;
        P.M = SB; P.N = EMB; P.K = DSS;
        launch_gemm<5>(P);
    }

    // 9. stack_inp = nonsat(ht @ D_w^T + D_b)
    {
        GemmArgs P{};
        P.A0 = ht; P.W0 = t_Dw; P.b0 = D_b; P.C = si;
        P.M = SB; P.N = SWIDTH; P.K = EMB;
        launch_gemm<6>(P);
    }

    // 10. controls
    controls_kernel<<<SB, 128>>>(out_hidden, A_w, A_b, ctl);

    // 11. stack update
    stack_kernel<<<SB, 128>>>(stack_prev, si, ctl, out_stack);

    // 12. LN2 (tf32-rounded output)
    ln_kernel<<<SB, 128>>>(xb, ln2_g, ln2_b, h2);

    // 13. FF1 (relu, tf32-rounded output)
    {
        GemmArgs P{};
        P.A0 = h2; P.W0 = t_ff1; P.b0 = ff_b1; P.C = f1;
        P.M = SB; P.N = DFF; P.K = EMB;
        launch_gemm<1>(P);
    }

    // 14. FF2 + residual -> out_x
    {
        GemmArgs P{};
        P.A0 = f1; P.W0 = t_ff2; P.b0 = ff_b2; P.res = xb; P.C = out_x;
        P.M = SB; P.N = EMB; P.K = DFF;
        launch_gemm<2>(P);
    }
}

// round 12
// speedup vs baseline: 1.8866x; 1.1027x over previous
#include <cuda_runtime.h>
#include <cuda_bf16.h>
#include <cstdint>

// Problem dims
#define SEQ 512
#define BATCH 16
#define EMB 512
#define SB 8192           // SEQ*BATCH rows
#define DFF 2048
#define DSS 128
#define SDEPTH 48
#define SWIDTH 128
#define NHEADS 8
#define HDIM 64

// ---------------- scratch (device globals; no allocation) ----------------
__device__ float g_h1 [SB * EMB];
__device__ float g_qkv[SB * 3 * EMB];
__device__ float g_att[SB * EMB];
__device__ float g_x  [SB * EMB];
__device__ float g_xt [SB * EMB];      // tf32-rounded copy of x
__device__ float g_ht [SB * EMB];      // tf32-rounded copy of hidden
__device__ float g_hpt[SB * EMB];      // tf32-rounded hidden_prev
__device__ float g_stt[SB * SWIDTH];   // tf32-rounded stack top slice
__device__ float g_lg [SB * DSS];
__device__ float g_si [SB * SWIDTH];
__device__ float g_h2 [SB * EMB];
__device__ float g_f1 [SB * DFF];
__device__ float g_wt [3997696];       // tf32-rounded weights pool

// ---------------- helpers ----------------
__device__ __forceinline__ float nonsat_f(float x) {
    float y = x;
#pragma unroll
    for (int i = 0; i < 20; i++) {
        float y2 = y * y;
        y = __fdividef(0.6666666666666666f * y2 * y + x, y2 + 1.0f);
    }
    return y;
}

__device__ __forceinline__ uint32_t to_tf32(float x) {
    uint32_t r;
    asm("cvt.rna.tf32.f32 %0, %1;" : "=r"(r) : "f"(x));
    return r;
}
__device__ __forceinline__ float rtf(float x) { return __uint_as_float(to_tf32(x)); }

__device__ __forceinline__ void mma_tf32(float (&c)[4], const uint32_t (&a)[4], const uint32_t (&b)[2]) {
    asm volatile(
        "mma.sync.aligned.m16n8k8.row.col.f32.tf32.tf32.f32 "
        "{%0,%1,%2,%3},{%4,%5,%6,%7},{%8,%9},{%0,%1,%2,%3};"
        : "+f"(c[0]), "+f"(c[1]), "+f"(c[2]), "+f"(c[3])
        : "r"(a[0]), "r"(a[1]), "r"(a[2]), "r"(a[3]), "r"(b[0]), "r"(b[1]));
}

__device__ __forceinline__ void ldsm4(uint32_t& r0, uint32_t& r1, uint32_t& r2, uint32_t& r3,
                                      uint32_t addr) {
    asm volatile("ldmatrix.sync.aligned.m8n8.x4.shared.b16 {%0,%1,%2,%3}, [%4];"
                 : "=r"(r0), "=r"(r1), "=r"(r2), "=r"(r3) : "r"(addr));
}

__device__ __forceinline__ void cp16(uint32_t dst, const float* src) {
    asm volatile("cp.async.cg.shared.global [%0], [%1], 16;" :: "r"(dst), "l"(src));
}
#define CP_COMMIT() asm volatile("cp.async.commit_group;")
#define CP_WAIT1()  asm volatile("cp.async.wait_group 1;")

// ---------------- pre-round pass: tf32-round tensors into scratch ----------------
struct RoundEntry { const float* src; float* dst; int n; int shift; int mask; int stride; };
struct RoundArgs { RoundEntry e[12]; };

__global__ void __launch_bounds__(256) round_multi(RoundArgs A) {
    const int gs = gridDim.x * blockDim.x;
    const int t0 = blockIdx.x * blockDim.x + threadIdx.x;
#pragma unroll 1
    for (int i = 0; i < 12; i++) {
        const RoundEntry E = A.e[i];
        for (int idx = t0; idx < E.n; idx += gs) {
            int row = idx >> E.shift;
            int col = idx & E.mask;
            E.dst[idx] = rtf(E.src[(size_t)row * E.stride + col]);
        }
    }
}

// ---------------- GEMM: C[M,N] = A[M,K] @ W[N,K]^T + epilogue ----------------
struct GemmArgs {
    const float* A0; const float* A1; const float* A2;
    const float* W0; const float* W1; const float* W2;
    const float* b0; const float* b1; const float* b2;
    const float* res;
    float* C;
    float* C2;
    int M, N, K;
};

// MODE: 0=+bias  1=+bias,relu,round  2=+bias+res(+C2 round)  3=hidden(3src,+3bias,nonsat,+C2)
//       4=logits(2src,nobias)  5=mix(res: 0.5*(res+acc))  6=+bias,nonsat
template<int MODE>
__device__ __forceinline__ const float* addrA(const GemmArgs& P, int grow, int gk) {
    if constexpr (MODE == 3) {
        if (gk < 512) {
            int xr = ((grow & 511) << 4) + (grow >> 9);
            return &P.A0[(size_t)xr * 512 + gk];
        } else if (gk < 1024) {
            return &P.A1[(size_t)grow * 512 + (gk - 512)];
        } else {
            return &P.A2[(size_t)grow * 128 + (gk - 1024)];
        }
    } else if constexpr (MODE == 4) {
        if (gk < 512) return &P.A0[(size_t)grow * 512 + gk];
        int hr = ((grow & 15) << 9) + (grow >> 4);
        return &P.A1[(size_t)hr * 512 + (gk - 512)];
    } else {
        return &P.A0[(size_t)grow * (size_t)P.K + gk];
    }
}

template<int MODE>
__device__ __forceinline__ const float* addrW(const GemmArgs& P, int n, int gk) {
    if constexpr (MODE == 3) {
        if (gk < 512)       return &P.W0[(size_t)n * 512 + gk];
        else if (gk < 1024) return &P.W1[(size_t)n * 512 + (gk - 512)];
        else                return &P.W2[(size_t)n * 128 + (gk - 1024)];
    } else {
        return &P.W0[(size_t)n * (size_t)P.K + gk];
    }
}

// Tile (32*MT) x 128 x 16, 256 threads = 8 warps (2 x 4), 3-stage cp.async ring.
// Consumer fragments via ldmatrix.x4 (conflict-free with crosswise swizzle).
template<int MODE, int MT>
__global__ void __launch_bounds__(256) gemm_tc(GemmArgs P) {
    constexpr int AROWS = 32 * MT;         // 128 or 64
    constexpr int ALI = MT / 2;            // A loader passes (2 or 1)
    __shared__ uint32_t As[3][AROWS * 16];
    __shared__ uint32_t Bs[3][2048];

    const int tid  = threadIdx.x;
    const int lane = tid & 31;
    const int warp = tid >> 5;
    const int wm = warp >> 2;
    const int wn = warp & 3;
    const int bn = blockIdx.x, bm = blockIdx.y;
    const int row0 = bm * AROWS, col0 = bn * 128;

    const int r0 = tid >> 2;
    const int c4 = tid & 3;

    const int nst = P.K >> 4;

    int offsA[2], offsB[2];
    uint32_t rA[2], rB[2];
#pragma unroll
    for (int li = 0; li < ALI; li++) {
        int r = r0 + li * 64;
        offsA[li] = r * 16 + ((c4 ^ ((r >> 1) & 3)) << 2);
        rA[li] = row0 + r;
    }
#pragma unroll
    for (int li = 0; li < 2; li++) {
        int r = r0 + li * 64;
        offsB[li] = r * 16 + ((c4 ^ ((r >> 1) & 3)) << 2);
        rB[li] = col0 + r;
    }

    uint32_t sA[3], sB[3];
#pragma unroll
    for (int i = 0; i < 3; i++) {
        sA[i] = (uint32_t)__cvta_generic_to_shared(&As[i][0]);
        sB[i] = (uint32_t)__cvta_generic_to_shared(&Bs[i][0]);
    }

    auto issue = [&](int s, int b) {
        int kt = (s << 4) + c4 * 4;
#pragma unroll
        for (int li = 0; li < ALI; li++)
            cp16(sA[b] + offsA[li] * 4, addrA<MODE>(P, rA[li], kt));
#pragma unroll
        for (int li = 0; li < 2; li++)
            cp16(sB[b] + offsB[li] * 4, addrW<MODE>(P, rB[li], kt));
    };

    issue(0, 0);
    CP_COMMIT();
    if (nst > 1) issue(1, 1);
    CP_COMMIT();

    float acc[MT][4][4];
#pragma unroll
    for (int i = 0; i < MT; i++)
#pragma unroll
        for (int j = 0; j < 4; j++)
#pragma unroll
            for (int e = 0; e < 4; e++) acc[i][j][e] = 0.f;

    // ldmatrix lane decomposition
    const int m_ = lane >> 3, rr = lane & 7;

    int buf = 0, pbuf = 2;
#pragma unroll 1
    for (int s = 0; s < nst; s++) {
        CP_WAIT1();
        __syncthreads();
        if (s + 2 < nst) issue(s + 2, pbuf);
        CP_COMMIT();

#pragma unroll
        for (int ks = 0; ks < 2; ks++) {
            uint32_t af[MT][4];
            uint32_t bf[4][2];
#pragma unroll
            for (int tm = 0; tm < MT; tm++) {
                int row = wm * (16 * MT) + tm * 16 + ((m_ & 1) << 3) + rr;
                int grp = (2 * ks + (m_ >> 1)) ^ ((row >> 1) & 3);
                ldsm4(af[tm][0], af[tm][1], af[tm][2], af[tm][3],
                      sA[buf] + (row * 16 + (grp << 2)) * 4);
            }
#pragma unroll
            for (int tp = 0; tp < 2; tp++) {
                int row = wn * 32 + tp * 16 + ((m_ >> 1) << 3) + rr;
                int grp = (2 * ks + (m_ & 1)) ^ ((row >> 1) & 3);
                ldsm4(bf[2 * tp][0], bf[2 * tp][1], bf[2 * tp + 1][0], bf[2 * tp + 1][1],
                      sB[buf] + (row * 16 + (grp << 2)) * 4);
            }
#pragma unroll
            for (int tm = 0; tm < MT; tm++)
#pragma unroll
                for (int tn = 0; tn < 4; tn++)
                    mma_tf32(acc[tm][tn], af[tm], bf[tn]);
        }
        buf  = (buf == 2)  ? 0 : buf + 1;
        pbuf = (pbuf == 2) ? 0 : pbuf + 1;
    }

    const int g = lane >> 2;
    const int q = lane & 3;
#pragma unroll
    for (int tmi = 0; tmi < MT; tmi++) {
        int rb = row0 + wm * (16 * MT) + tmi * 16;
#pragma unroll
        for (int h2 = 0; h2 < 2; h2++) {
            int gm = rb + g + h2 * 8;
#pragma unroll
            for (int tni = 0; tni < 4; tni++) {
                int gn = col0 + wn * 32 + tni * 8 + q * 2;
                float v0 = acc[tmi][tni][h2 * 2 + 0];
                float v1 = acc[tmi][tni][h2 * 2 + 1];
                if constexpr (MODE == 0) { v0 += P.b0[gn]; v1 += P.b0[gn + 1]; }
                else if constexpr (MODE == 1) {
                    v0 = rtf(fmaxf(v0 + P.b0[gn], 0.f));
                    v1 = rtf(fmaxf(v1 + P.b0[gn + 1], 0.f));
                } else if constexpr (MODE == 2) {
                    const float* rp = &P.res[(size_t)gm * P.N + gn];
                    v0 = v0 + P.b0[gn] + rp[0];
                    v1 = v1 + P.b0[gn + 1] + rp[1];
                } else if constexpr (MODE == 3) {
                    v0 = nonsat_f(v0 + P.b0[gn] + P.b1[gn] + P.b2[gn]);
                    v1 = nonsat_f(v1 + P.b0[gn + 1] + P.b1[gn + 1] + P.b2[gn + 1]);
                } else if constexpr (MODE == 4) {
                    /* raw */
                } else if constexpr (MODE == 5) {
                    const float* rp = &P.res[(size_t)gm * P.N + gn];
                    v0 = 0.5f * (rp[0] + v0);
                    v1 = 0.5f * (rp[1] + v1);
                } else if constexpr (MODE == 6) {
                    v0 = nonsat_f(v0 + P.b0[gn]);
                    v1 = nonsat_f(v1 + P.b0[gn + 1]);
                }
                *(float2*)&P.C[(size_t)gm * P.N + gn] = make_float2(v0, v1);
                if constexpr (MODE == 2 || MODE == 3) {
                    if (P.C2)
                        *(float2*)&P.C2[(size_t)gm * P.N + gn] = make_float2(rtf(v0), rtf(v1));
                }
            }
        }
    }
}

// ---------------- LayerNorm (row of 512), output tf32-rounded ----------------
__global__ void __launch_bounds__(128) ln_kernel(const float* __restrict__ x,
                                                 const float* __restrict__ g,
                                                 const float* __restrict__ b,
                                                 float* __restrict__ out) {
    const int r = blockIdx.x, t = threadIdx.x;
    const float* row = x + (size_t)r * 512;
    float v0 = row[t], v1 = row[t + 128], v2 = row[t + 256], v3 = row[t + 384];
    __shared__ float sh[4];
    float s = v0 + v1 + v2 + v3;
#pragma unroll
    for (int o = 16; o; o >>= 1) s += __shfl_xor_sync(0xffffffffu, s, o);
    if ((t & 31) == 0) sh[t >> 5] = s;
    __syncthreads();
    float mean = (sh[0] + sh[1] + sh[2] + sh[3]) * (1.f / 512.f);
    __syncthreads();
    float d0 = v0 - mean, d1 = v1 - mean, d2 = v2 - mean, d3 = v3 - mean;
    float q = d0 * d0 + d1 * d1 + d2 * d2 + d3 * d3;
#pragma unroll
    for (int o = 16; o; o >>= 1) q += __shfl_xor_sync(0xffffffffu, q, o);
    if ((t & 31) == 0) sh[t >> 5] = q;
    __syncthreads();
    float var = (sh[0] + sh[1] + sh[2] + sh[3]) * (1.f / 512.f);
    float rstd = rsqrtf(var + 1e-5f);
    float* orow = out + (size_t)r * 512;
    orow[t]       = rtf(d0 * rstd * g[t]       + b[t]);
    orow[t + 128] = rtf(d1 * rstd * g[t + 128] + b[t + 128]);
    orow[t + 256] = rtf(d2 * rstd * g[t + 256] + b[t + 256]);
    orow[t + 384] = rtf(d3 * rstd * g[t + 384] + b[t + 384]);
}

// ---------------- Flash attention, tf32 tensor-core (64x64 tiles, causal) ------
#define AP 72
__global__ void __launch_bounds__(256) attn_kernel(const float* __restrict__ qkv,
                                                   const unsigned char* __restrict__ kmask,
                                                   float* __restrict__ out) {
    extern __shared__ float sm[];
    float* Qs   = sm;
    float* Ks   = Qs + 64 * AP;
    float* Vt   = Ks + 64 * AP;
    float* Ps   = Vt + 64 * AP;
    float* Pt   = Ps + 64 * AP;
    float* mrow = Pt + 64 * 68;
    float* lrow = mrow + 64;
    float* rsc  = lrow + 64;
    float* kmf  = rsc + 64;

    const int tid = threadIdx.x;
    const int qt = blockIdx.x;
    const int bh = blockIdx.y;
    const int b = bh >> 3, h = bh & 7;
    const int lane = tid & 31;
    const int warp = tid >> 5;
    const int wrow = warp >> 2;
    const int wcol = warp & 3;
    const int g  = lane >> 2;
    const int kq = lane & 3;

#pragma unroll
    for (int li = 0; li < 4; li++) {
        int idx = tid + li * 256;
        int g4 = idx & 15, r = idx >> 4;
        const float4 q = *(const float4*)&qkv[(size_t)((qt * 64 + r) * 16 + b) * 1536 + h * 64 + g4 * 4];
        float* d = &Qs[r * AP + ((g4 ^ (r & 7)) << 2)];
        d[0] = rtf(q.x * 0.125f);
        d[1] = rtf(q.y * 0.125f);
        d[2] = rtf(q.z * 0.125f);
        d[3] = rtf(q.w * 0.125f);
    }
    if (tid < 64) { mrow[tid] = -1e30f; lrow[tid] = 0.f; }

    float Oa[2][2][4];
#pragma unroll
    for (int i = 0; i < 2; i++)
#pragma unroll
        for (int j = 0; j < 2; j++)
#pragma unroll
            for (int e = 0; e < 4; e++) Oa[i][j][e] = 0.f;
    __syncthreads();

    const int rb0 = wrow * 32;
    const int cb0 = wcol * 16;

    for (int kt = 0; kt <= qt; kt++) {
#pragma unroll
        for (int li = 0; li < 4; li++) {
            int idx = tid + li * 256;
            int g4 = idx & 15, c = idx >> 4;
            size_t base = (size_t)((kt * 64 + c) * 16 + b) * 1536 + h * 64;
            const float4 kv = *(const float4*)&qkv[base + 512 + g4 * 4];
            float* d = &Ks[c * AP + ((g4 ^ (c & 7)) << 2)];
            d[0] = rtf(kv.x); d[1] = rtf(kv.y); d[2] = rtf(kv.z); d[3] = rtf(kv.w);
        }
#pragma unroll
        for (int li = 0; li < 4; li++) {
            int idx = tid + li * 256;
            int c = idx & 63, d4 = idx >> 6;
            size_t base = (size_t)((kt * 64 + c) * 16 + b) * 1536 + h * 64 + 1024;
            const float4 vv = *(const float4*)&qkv[base + d4 * 4];
            float v[4] = {vv.x, vv.y, vv.z, vv.w};
#pragma unroll
            for (int j = 0; j < 4; j++) {
                int dd = d4 * 4 + j;
                Vt[dd * AP + (((c >> 2) ^ (dd & 7)) << 2) + (c & 3)] = rtf(v[j]);
            }
        }
        if (tid < 64) kmf[tid] = kmask[b * 512 + kt * 64 + tid] ? -1e30f : 0.f;
        __syncthreads();

        float sc[2][2][4];
#pragma unroll
        for (int i = 0; i < 2; i++)
#pragma unroll
            for (int j = 0; j < 2; j++)
#pragma unroll
                for (int e = 0; e < 4; e++) sc[i][j][e] = 0.f;
#pragma unroll
        for (int ks = 0; ks < 8; ks++) {
            const int G0 = ((2 * ks) ^ g) << 2;
            const int G1 = ((2 * ks + 1) ^ g) << 2;
            uint32_t af[2][4], bf[2][2];
#pragma unroll
            for (int tm = 0; tm < 2; tm++) {
                const uint32_t* A_ = (const uint32_t*)&Qs[(rb0 + tm * 16 + g) * AP + kq];
                af[tm][0] = A_[G0];
                af[tm][1] = A_[8 * AP + G0];
                af[tm][2] = A_[G1];
                af[tm][3] = A_[8 * AP + G1];
            }
#pragma unroll
            for (int tn = 0; tn < 2; tn++) {
                const uint32_t* B_ = (const uint32_t*)&Ks[(cb0 + tn * 8 + g) * AP + kq];
                bf[tn][0] = B_[G0];
                bf[tn][1] = B_[G1];
            }
#pragma unroll
            for (int tm = 0; tm < 2; tm++)
#pragma unroll
                for (int tn = 0; tn < 2; tn++)
                    mma_tf32(sc[tm][tn], af[tm], bf[tn]);
        }

        const bool diag = (kt == qt);
#pragma unroll
        for (int tm = 0; tm < 2; tm++) {
#pragma unroll
            for (int tn = 0; tn < 2; tn++) {
#pragma unroll
                for (int e = 0; e < 4; e++) {
                    int r = rb0 + tm * 16 + g + (e >> 1) * 8;
                    int c = cb0 + tn * 8 + 2 * kq + (e & 1);
                    float val = sc[tm][tn][e] + kmf[c];
                    if (diag && c > r) val = -1e30f;
                    Pt[c * 68 + r] = val;
                }
            }
        }
        __syncthreads();

        {
            int r = tid >> 2, q4 = tid & 3;
            float mx = -1e30f;
#pragma unroll
            for (int cc = 0; cc < 16; cc++) mx = fmaxf(mx, Pt[(q4 * 16 + cc) * 68 + r]);
            mx = fmaxf(mx, __shfl_xor_sync(0xffffffffu, mx, 1));
            mx = fmaxf(mx, __shfl_xor_sync(0xffffffffu, mx, 2));
            float mold = mrow[r];
            float mnew = fmaxf(mold, mx);
            float sum = 0.f;
#pragma unroll
            for (int cc = 0; cc < 16; cc++) {
                int c = q4 * 16 + cc;
                float p = __expf(Pt[c * 68 + r] - mnew);
                Ps[r * AP + (((c >> 2) ^ (r & 7)) << 2) + (c & 3)] = rtf(p);
                sum += p;
            }
            sum += __shfl_xor_sync(0xffffffffu, sum, 1);
            sum += __shfl_xor_sync(0xffffffffu, sum, 2);
            if (q4 == 0) {
                float scale = __expf(mold - mnew);
                mrow[r] = mnew;
                lrow[r] = lrow[r] * scale + sum;
                rsc[r] = scale;
            }
        }
        __syncthreads();

#pragma unroll
        for (int tm = 0; tm < 2; tm++) {
            float s0 = rsc[rb0 + tm * 16 + g];
            float s1 = rsc[rb0 + tm * 16 + g + 8];
#pragma unroll
            for (int tn = 0; tn < 2; tn++) {
                Oa[tm][tn][0] *= s0; Oa[tm][tn][1] *= s0;
                Oa[tm][tn][2] *= s1; Oa[tm][tn][3] *= s1;
            }
        }
#pragma unroll
        for (int ks = 0; ks < 8; ks++) {
            const int G0 = ((2 * ks) ^ g) << 2;
            const int G1 = ((2 * ks + 1) ^ g) << 2;
            uint32_t af[2][4], bf[2][2];
#pragma unroll
            for (int tm = 0; tm < 2; tm++) {
                const uint32_t* A_ = (const uint32_t*)&Ps[(rb0 + tm * 16 + g) * AP + kq];
                af[tm][0] = A_[G0];
                af[tm][1] = A_[8 * AP + G0];
                af[tm][2] = A_[G1];
                af[tm][3] = A_[8 * AP + G1];
            }
#pragma unroll
            for (int tn = 0; tn < 2; tn++) {
                const uint32_t* B_ = (const uint32_t*)&Vt[(cb0 + tn * 8 + g) * AP + kq];
                bf[tn][0] = B_[G0];
                bf[tn][1] = B_[G1];
            }
#pragma unroll
            for (int tm = 0; tm < 2; tm++)
#pragma unroll
                for (int tn = 0; tn < 2; tn++)
                    mma_tf32(Oa[tm][tn], af[tm], bf[tn]);
        }
        __syncthreads();
    }

#pragma unroll
    for (int tm = 0; tm < 2; tm++) {
#pragma unroll
        for (int e2 = 0; e2 < 2; e2++) {
            int r = rb0 + tm * 16 + g + e2 * 8;
            float inv = __fdividef(1.f, lrow[r]);
#pragma unroll
            for (int tn = 0; tn < 2; tn++) {
                int d = cb0 + tn * 8 + 2 * kq;
                float v0 = rtf(Oa[tm][tn][e2 * 2 + 0] * inv);
                float v1 = rtf(Oa[tm][tn][e2 * 2 + 1] * inv);
                *(float2*)&out[(size_t)((qt * 64 + r) * 16 + b) * 512 + h * 64 + d] =
                    make_float2(v0, v1);
            }
        }
    }
}

// ---------------- softmax over 128 (mixture logits), output tf32-rounded -------
__global__ void __launch_bounds__(128) softmax128_kernel(float* __restrict__ lg) {
    const int r = blockIdx.x, t = threadIdx.x;
    float v = lg[(size_t)r * 128 + t];
    __shared__ float sh[4];
    float m = v;
#pragma unroll
    for (int o = 16; o; o >>= 1) m = fmaxf(m, __shfl_xor_sync(0xffffffffu, m, o));
    if ((t & 31) == 0) sh[t >> 5] = m;
    __syncthreads();
    m = fmaxf(fmaxf(sh[0], sh[1]), fmaxf(sh[2], sh[3]));
    float e = __expf(v - m);
    __syncthreads();
    float s = e;
#pragma unroll
    for (int o = 16; o; o >>= 1) s += __shfl_xor_sync(0xffffffffu, s, o);
    if ((t & 31) == 0) sh[t >> 5] = s;
    __syncthreads();
    s = sh[0] + sh[1] + sh[2] + sh[3];
    lg[(size_t)r * 128 + t] = rtf(e * __fdividef(1.f, s));
}

// ---------------- fused controls + stack update ----------------
__global__ void __launch_bounds__(128) stack_kernel(const float* __restrict__ stack_prev,
                                                    const float* __restrict__ si,
                                                    const float* __restrict__ hidden,
                                                    const float* __restrict__ Aw,
                                                    const float* __restrict__ Ab,
                                                    float* __restrict__ out) {
    const int g = blockIdx.x;       // b*512+s
    const int t = threadIdx.x;      // 0..127

    // controls = softmax(hidden_row @ Aw^T + Ab)
    const float* hrow = hidden + (size_t)g * 512;
    float s0 = 0.f, s1 = 0.f, s2 = 0.f;
#pragma unroll
    for (int i = 0; i < 4; i++) {
        int c = t + i * 128;
        float hv = hrow[c];
        s0 += hv * Aw[c];
        s1 += hv * Aw[512 + c];
        s2 += hv * Aw[1024 + c];
    }
    __shared__ float sh[3][4];
    __shared__ float bc[3];
#pragma unroll
    for (int o = 16; o; o >>= 1) {
        s0 += __shfl_xor_sync(0xffffffffu, s0, o);
        s1 += __shfl_xor_sync(0xffffffffu, s1, o);
        s2 += __shfl_xor_sync(0xffffffffu, s2, o);
    }
    if ((t & 31) == 0) { sh[0][t >> 5] = s0; sh[1][t >> 5] = s1; sh[2][t >> 5] = s2; }
    __syncthreads();
    if (t == 0) {
        float c0 = sh[0][0] + sh[0][1] + sh[0][2] + sh[0][3] + Ab[0];
        float c1 = sh[1][0] + sh[1][1] + sh[1][2] + sh[1][3] + Ab[1];
        float c2 = sh[2][0] + sh[2][1] + sh[2][2] + sh[2][3] + Ab[2];
        float m = fmaxf(c0, fmaxf(c1, c2));
        float e0 = __expf(c0 - m), e1 = __expf(c1 - m), e2 = __expf(c2 - m);
        float inv = __fdividef(1.f, e0 + e1 + e2);
        bc[0] = e0 * inv; bc[1] = e1 * inv; bc[2] = e2 * inv;
    }
    __syncthreads();
    const float cpush = bc[0], cpop = bc[1], cnoop = bc[2];

    const float* prev = stack_prev + (size_t)g * (SDEPTH * SWIDTH);
    float* o = out + (size_t)g * (SDEPTH * SWIDTH);
    float pm1 = si[(size_t)g * 128 + t];
    float p0 = prev[t];
#pragma unroll 4
    for (int d = 0; d < SDEPTH; d++) {
        float p1 = (d < SDEPTH - 1) ? prev[(d + 1) * SWIDTH + t] : 0.f;
        o[d * SWIDTH + t] = cnoop * p0 + cpush * pm1 + cpop * p1;
        pm1 = p0;
        p0 = p1;
    }
}

// ---------------- host ----------------
template<int MODE, int MT>
static void launch_gemm(const GemmArgs& P) {
    dim3 grid(P.N / 128, P.M / (32 * MT));
    gemm_tc<MODE, MT><<<grid, 256>>>(P);
}

extern "C" void kernel_launch(void* const* d_in, const int* in_sizes, int n_in,
                              void* d_out, int out_size) {
    const float* x_in        = (const float*)d_in[0];
    const float* hidden_prev = (const float*)d_in[1];
    const float* stack_prev  = (const float*)d_in[2];
    const unsigned char* k_mask = (const unsigned char*)d_in[3];
    const float* in_proj_w  = (const float*)d_in[4];
    const float* in_proj_b  = (const float*)d_in[5];
    const float* out_proj_w = (const float*)d_in[6];
    const float* out_proj_b = (const float*)d_in[7];
    const float* ln1_g = (const float*)d_in[8];
    const float* ln1_b = (const float*)d_in[9];
    const float* ln2_g = (const float*)d_in[10];
    const float* ln2_b = (const float*)d_in[11];
    const float* ff_w1 = (const float*)d_in[12];
    const float* ff_b1 = (const float*)d_in[13];
    const float* ff_w2 = (const float*)d_in[14];
    const float* ff_b2 = (const float*)d_in[15];
    const float* W_w = (const float*)d_in[16];
    const float* W_b = (const float*)d_in[17];
    const float* R_w = (const float*)d_in[18];
    const float* R_b = (const float*)d_in[19];
    const float* P_w = (const float*)d_in[20];
    const float* P_b = (const float*)d_in[21];
    const float* V_w = (const float*)d_in[22];
    const float* U_w = (const float*)d_in[23];
    const float* A_w = (const float*)d_in[24];
    const float* A_b = (const float*)d_in[25];
    const float* D_w = (const float*)d_in[26];
    const float* D_b = (const float*)d_in[27];

    float *h1, *qkvb, *attb, *xb, *xt, *ht, *hpt, *stt, *lg, *si, *h2, *f1, *wt;
    cudaGetSymbolAddress((void**)&h1,  g_h1);
    cudaGetSymbolAddress((void**)&qkvb, g_qkv);
    cudaGetSymbolAddress((void**)&attb, g_att);
    cudaGetSymbolAddress((void**)&xb,  g_x);
    cudaGetSymbolAddress((void**)&xt,  g_xt);
    cudaGetSymbolAddress((void**)&ht,  g_ht);
    cudaGetSymbolAddress((void**)&hpt, g_hpt);
    cudaGetSymbolAddress((void**)&stt, g_stt);
    cudaGetSymbolAddress((void**)&lg,  g_lg);
    cudaGetSymbolAddress((void**)&si,  g_si);
    cudaGetSymbolAddress((void**)&h2,  g_h2);
    cudaGetSymbolAddress((void**)&f1,  g_f1);
    cudaGetSymbolAddress((void**)&wt,  g_wt);

    float* t_inproj = wt + 0;
    float* t_outprj = wt + 786432;
    float* t_Ww     = wt + 1048576;
    float* t_Rw     = wt + 1310720;
    float* t_Pw     = wt + 1572864;
    float* t_Vw     = wt + 1638400;
    float* t_Uw     = wt + 1769472;
    float* t_Dw     = wt + 1835008;
    float* t_ff1    = wt + 1900544;
    float* t_ff2    = wt + 2949120;

    float* out_x      = (float*)d_out;
    float* out_hidden = out_x + (size_t)SB * EMB;
    float* out_stack  = out_hidden + (size_t)SB * EMB;

    const int ATTN_SMEM = (4 * 64 * AP + 64 * 68 + 4 * 64) * (int)sizeof(float);
    cudaFuncSetAttribute(attn_kernel, cudaFuncAttributeMaxDynamicSharedMemorySize, ATTN_SMEM);

    // 0. pre-round weights + hidden_prev + stack top to tf32-exact fp32
    {
        const int FM = 0x3FFFFFFF;
        RoundArgs RA{};
        RA.e[0]  = {in_proj_w,  t_inproj, 786432,  30, FM, 0};
        RA.e[1]  = {out_proj_w, t_outprj, 262144,  30, FM, 0};
        RA.e[2]  = {W_w,        t_Ww,     262144,  30, FM, 0};
        RA.e[3]  = {R_w,        t_Rw,     262144,  30, FM, 0};
        RA.e[4]  = {P_w,        t_Pw,     65536,   30, FM, 0};
        RA.e[5]  = {V_w,        t_Vw,     131072,  30, FM, 0};
        RA.e[6]  = {U_w,        t_Uw,     65536,   30, FM, 0};
        RA.e[7]  = {D_w,        t_Dw,     65536,   30, FM, 0};
        RA.e[8]  = {ff_w1,      t_ff1,    1048576, 30, FM, 0};
        RA.e[9]  = {ff_w2,      t_ff2,    1048576, 30, FM, 0};
        RA.e[10] = {hidden_prev, hpt,     SB * EMB, 30, FM, 0};
        RA.e[11] = {stack_prev,  stt,     SB * SWIDTH, 7, 127, SDEPTH * SWIDTH};
        round_multi<<<2048, 256>>>(RA);
    }

    // 1. LN1
    ln_kernel<<<SB, 128>>>(x_in, ln1_g, ln1_b, h1);

    // 2. QKV projection
    {
        GemmArgs P{};
        P.A0 = h1; P.W0 = t_inproj; P.b0 = in_proj_b; P.C = qkvb;
        P.M = SB; P.N = 3 * EMB; P.K = EMB;
        launch_gemm<0, 4>(P);
    }

    // 3. Attention
    attn_kernel<<<dim3(SEQ / 64, BATCH * NHEADS), 256, ATTN_SMEM>>>(qkvb, k_mask, attb);

    // 4. Output projection + residual -> x + xt
    {
        GemmArgs P{};
        P.A0 = attb; P.W0 = t_outprj; P.b0 = out_proj_b; P.res = x_in;
        P.C = xb; P.C2 = xt;
        P.M = SB; P.N = EMB; P.K = EMB;
        launch_gemm<2, 4>(P);
    }

    // 5. hidden = nonsat(xt@W^T + hpt@R^T + stt@P^T + biases) -> out_hidden + ht
    {
        GemmArgs P{};
        P.A0 = xt; P.A1 = hpt; P.A2 = stt;
        P.W0 = t_Ww; P.W1 = t_Rw; P.W2 = t_Pw;
        P.b0 = W_b; P.b1 = R_b; P.b2 = P_b;
        P.C = out_hidden; P.C2 = ht;
        P.M = SB; P.N = EMB; P.K = 1152;
        launch_gemm<3, 4>(P);
    }

    // 6. logits = [xt | ht^T] @ V_w^T  (N=128 -> MT=2 for full-chip wave)
    {
        GemmArgs P{};
        P.A0 = xt; P.A1 = ht; P.W0 = t_Vw; P.C = lg;
        P.M = SB; P.N = DSS; P.K = 1024;
        launch_gemm<4, 2>(P);
    }

    // 7. softmax over 128
    softmax128_kernel<<<SB, 128>>>(lg);

    // 8. x = 0.5*(x + p @ U_w^T)
    {
        GemmArgs P{};
        P.A0 = lg; P.W0 = t_Uw; P.res = xb; P.C = xb;
        P.M = SB; P.N = EMB; P.K = DSS;
        launch_gemm<5, 4>(P);
    }

    // 9. stack_inp = nonsat(ht @ D_w^T + D_b)  (N=128 -> MT=2)
    {
        GemmArgs P{};
        P.A0 = ht; P.W0 = t_Dw; P.b0 = D_b; P.C = si;
        P.M = SB; P.N = SWIDTH; P.K = EMB;
        launch_gemm<6, 2>(P);
    }

    // 10. fused controls + stack update
    stack_kernel<<<SB, 128>>>(stack_prev, si, out_hidden, A_w, A_b, out_stack);

    // 11. LN2
    ln_kernel<<<SB, 128>>>(xb, ln2_g, ln2_b, h2);

    // 12. FF1 (relu)
    {
        GemmArgs P{};
        P.A0 = h2; P.W0 = t_ff1; P.b0 = ff_b1; P.C = f1;
        P.M = SB; P.N = DFF; P.K = EMB;
        launch_gemm<1, 4>(P);
    }

    // 13. FF2 + residual -> out_x
    {
        GemmArgs P{};
        P.A0 = f1; P.W0 = t_ff2; P.b0 = ff_b2; P.res = xb; P.C = out_x;
        P.M = SB; P.N = EMB; P.K = DFF;
        launch_gemm<2, 4>(P);
    }
}